// round 1
// baseline (speedup 1.0000x reference)
#include <cuda_runtime.h>
#include <cuda_bf16.h>
#include <cstdint>
#include <cstddef>

// ---------------- problem constants ----------------
#define B_      256
#define T_      14
#define E_RAW   300
#define E_PAD   320        // pad K to multiple of 32
#define QH      1024
#define G4H     4096
#define ICNN    2048
#define MAXN_   100
#define HID_    512
#define ROWS_BIG (B_*MAXN_)   // 25600
#define NBIG     1024          // interleaved 2*HID

// ---------------- device scratch (static, allocation-free) ----------------
__device__ __nv_bfloat16 g_Xbf [(size_t)T_*B_*E_PAD];     // LSTM input, t-major, padded
__device__ __nv_bfloat16 g_Wih [(size_t)G4H*E_PAD];       // gate-interleaved rows, padded K
__device__ __nv_bfloat16 g_Whh [(size_t)G4H*QH];          // gate-interleaved rows
__device__ float         g_bias[G4H];                     // b_ih+b_hh, gate-interleaved
__device__ float         g_Xg  [(size_t)T_*B_*G4H];       // input projections (fp32)
__device__ float         g_G   [(size_t)B_*G4H];          // recurrent pre-gates per step
__device__ float         g_c   [(size_t)B_*QH];           // LSTM cell state
__device__ __nv_bfloat16 g_h   [(size_t)B_*QH];           // LSTM hidden (bf16)
__device__ __nv_bfloat16 g_Wbox[(size_t)NBIG*ICNN];       // rows 2h=W_w[h,:2048], 2h+1=Wp_w
__device__ __nv_bfloat16 g_Wq  [(size_t)NBIG*QH];         // rows 2h=W_w[h,2048:], 2h+1=Wp_w
__device__ float         g_mb  [NBIG];                    // interleaved W_b / Wp_b
__device__ float         g_fw  [HID_];
__device__ float         g_qp  [(size_t)B_*NBIG];         // question projections
__device__ __nv_bfloat16 g_box [(size_t)ROWS_BIG*ICNN];   // box feats bf16
__device__ float         g_Z   [(size_t)ROWS_BIG*NBIG];   // box-part pre-activations
__device__ float         g_wsi [ROWS_BIG];

// ---------------- mma.sync m16n8k16 bf16 ----------------
__device__ __forceinline__ void mma16816(float acc[4], const uint32_t a[4], const uint32_t b[2]) {
    asm volatile(
        "mma.sync.aligned.m16n8k16.row.col.f32.bf16.bf16.f32 "
        "{%0,%1,%2,%3}, {%4,%5,%6,%7}, {%8,%9}, {%0,%1,%2,%3};\n"
        : "+f"(acc[0]), "+f"(acc[1]), "+f"(acc[2]), "+f"(acc[3])
        : "r"(a[0]), "r"(a[1]), "r"(a[2]), "r"(a[3]), "r"(b[0]), "r"(b[1]));
}

// C[M,N] (fp32) = A[M,K] * B[N,K]^T, bf16 inputs, row-major, K%32==0, M%128==0, N%128==0.
// Tile 128x128x32, 256 threads (8 warps, 2x4), warp tile 64x32.
__global__ __launch_bounds__(256) void gemm_bf16_nt(
    const __nv_bfloat16* __restrict__ A,
    const __nv_bfloat16* __restrict__ B,
    float* __restrict__ C,
    int K, int N)
{
    __shared__ __align__(16) __nv_bfloat16 sA[128][40];   // 32 + 8 pad (conflict-free)
    __shared__ __align__(16) __nv_bfloat16 sB[128][40];

    const int tid  = threadIdx.x;
    const int warp = tid >> 5;
    const int lane = tid & 31;
    const int wm   = warp >> 2;       // 0..1
    const int wn   = warp & 3;        // 0..3
    const int g    = lane >> 2;       // 0..7
    const int tt   = lane & 3;        // 0..3

    const size_t m0 = (size_t)blockIdx.y * 128;
    const size_t n0 = (size_t)blockIdx.x * 128;

    const int r0  = tid >> 2;         // rows 0..63
    const int ch0 = tid & 3;          // 4 x uint4 (8 bf16) chunks per 32-wide row
    const int r1  = r0 + 64;

    const __nv_bfloat16* Ag0 = A + (m0 + r0) * (size_t)K + ch0 * 8;
    const __nv_bfloat16* Ag1 = A + (m0 + r1) * (size_t)K + ch0 * 8;
    const __nv_bfloat16* Bg0 = B + (n0 + r0) * (size_t)K + ch0 * 8;
    const __nv_bfloat16* Bg1 = B + (n0 + r1) * (size_t)K + ch0 * 8;

    float acc[4][4][4];
    #pragma unroll
    for (int mi = 0; mi < 4; mi++)
        #pragma unroll
        for (int ni = 0; ni < 4; ni++)
            #pragma unroll
            for (int e = 0; e < 4; e++) acc[mi][ni][e] = 0.f;

    for (int k0 = 0; k0 < K; k0 += 32) {
        uint4 av0 = *(const uint4*)(Ag0 + k0);
        uint4 av1 = *(const uint4*)(Ag1 + k0);
        uint4 bv0 = *(const uint4*)(Bg0 + k0);
        uint4 bv1 = *(const uint4*)(Bg1 + k0);
        __syncthreads();
        *(uint4*)&sA[r0][ch0 * 8] = av0;
        *(uint4*)&sA[r1][ch0 * 8] = av1;
        *(uint4*)&sB[r0][ch0 * 8] = bv0;
        *(uint4*)&sB[r1][ch0 * 8] = bv1;
        __syncthreads();

        #pragma unroll
        for (int kk = 0; kk < 2; kk++) {
            const int kb = kk * 16 + tt * 2;
            uint32_t af[4][4];
            uint32_t bfr[4][2];
            #pragma unroll
            for (int mi = 0; mi < 4; mi++) {
                const int r = wm * 64 + mi * 16;
                af[mi][0] = *(const uint32_t*)&sA[r + g    ][kb];
                af[mi][1] = *(const uint32_t*)&sA[r + 8 + g][kb];
                af[mi][2] = *(const uint32_t*)&sA[r + g    ][kb + 8];
                af[mi][3] = *(const uint32_t*)&sA[r + 8 + g][kb + 8];
            }
            #pragma unroll
            for (int ni = 0; ni < 4; ni++) {
                const int cc = wn * 32 + ni * 8;
                bfr[ni][0] = *(const uint32_t*)&sB[cc + g][kb];
                bfr[ni][1] = *(const uint32_t*)&sB[cc + g][kb + 8];
            }
            #pragma unroll
            for (int mi = 0; mi < 4; mi++)
                #pragma unroll
                for (int ni = 0; ni < 4; ni++)
                    mma16816(acc[mi][ni], af[mi], bfr[ni]);
        }
    }

    #pragma unroll
    for (int mi = 0; mi < 4; mi++) {
        const size_t row = m0 + wm * 64 + mi * 16 + g;
        #pragma unroll
        for (int ni = 0; ni < 4; ni++) {
            const size_t col = n0 + wn * 32 + ni * 8 + tt * 2;
            float2 v01 = make_float2(acc[mi][ni][0], acc[mi][ni][1]);
            float2 v23 = make_float2(acc[mi][ni][2], acc[mi][ni][3]);
            *(float2*)&C[row       * (size_t)N + col] = v01;
            *(float2*)&C[(row + 8) * (size_t)N + col] = v23;
        }
    }
}

// ---------------- prep kernels ----------------
// gate-interleaved source row: output row j -> gate (j&3), hidden (j>>2)
__device__ __forceinline__ int lstm_src_row(int j) { return (j & 3) * QH + (j >> 2); }

__global__ void prep_x_kernel(const float* __restrict__ q_feats) {
    int idx = blockIdx.x * blockDim.x + threadIdx.x;
    if (idx >= T_ * B_ * E_PAD) return;
    int r = idx / E_PAD, e = idx % E_PAD;
    int t = r >> 8, b = r & 255;                      // r = t*256 + b
    float v = (e < E_RAW) ? q_feats[((size_t)b * T_ + t) * E_RAW + e] : 0.f;
    g_Xbf[idx] = __float2bfloat16(v);
}

__global__ void prep_wih_kernel(const float* __restrict__ W_ih) {
    int idx = blockIdx.x * blockDim.x + threadIdx.x;
    if (idx >= G4H * E_PAD) return;
    int j = idx / E_PAD, e = idx % E_PAD;
    int src = lstm_src_row(j);
    float v = (e < E_RAW) ? W_ih[(size_t)src * E_RAW + e] : 0.f;
    g_Wih[idx] = __float2bfloat16(v);
}

__global__ void prep_whh_kernel(const float* __restrict__ W_hh) {
    int idx = blockIdx.x * blockDim.x + threadIdx.x;
    if (idx >= G4H * QH) return;
    int j = idx >> 10, e = idx & 1023;
    int src = lstm_src_row(j);
    g_Whh[idx] = __float2bfloat16(W_hh[(size_t)src * QH + e]);
}

__global__ void prep_bias_kernel(const float* __restrict__ b_ih, const float* __restrict__ b_hh) {
    int j = blockIdx.x * blockDim.x + threadIdx.x;
    if (j >= G4H) return;
    int src = lstm_src_row(j);
    g_bias[j] = b_ih[src] + b_hh[src];
}

__global__ void prep_wbox_kernel(const float* __restrict__ W_w, const float* __restrict__ Wp_w) {
    int idx = blockIdx.x * blockDim.x + threadIdx.x;
    if (idx >= NBIG * ICNN) return;
    int j = idx >> 11, cc = idx & 2047;
    int h = j >> 1;
    const float* s = (j & 1) ? Wp_w : W_w;
    g_Wbox[idx] = __float2bfloat16(s[(size_t)h * (ICNN + QH) + cc]);
}

__global__ void prep_wq_kernel(const float* __restrict__ W_w, const float* __restrict__ Wp_w) {
    int idx = blockIdx.x * blockDim.x + threadIdx.x;
    if (idx >= NBIG * QH) return;
    int j = idx >> 10, cc = idx & 1023;
    int h = j >> 1;
    const float* s = (j & 1) ? Wp_w : W_w;
    g_Wq[idx] = __float2bfloat16(s[(size_t)h * (ICNN + QH) + ICNN + cc]);
}

__global__ void prep_small_kernel(const float* __restrict__ W_b, const float* __restrict__ Wp_b,
                                  const float* __restrict__ f_w) {
    int idx = blockIdx.x * blockDim.x + threadIdx.x;
    if (idx < NBIG) {
        g_mb[idx] = (idx & 1) ? Wp_b[idx >> 1] : W_b[idx >> 1];
    } else if (idx < NBIG + HID_) {
        g_fw[idx - NBIG] = f_w[idx - NBIG];
    }
}

__global__ void conv_box_kernel(const float* __restrict__ box) {
    size_t i = ((size_t)blockIdx.x * blockDim.x + threadIdx.x) * 4;   // grid sized exactly
    float4 v = *(const float4*)(box + i);
    __nv_bfloat162 p0 = __floats2bfloat162_rn(v.x, v.y);
    __nv_bfloat162 p1 = __floats2bfloat162_rn(v.z, v.w);
    *(__nv_bfloat162*)(g_box + i)     = p0;
    *(__nv_bfloat162*)(g_box + i + 2) = p1;
}

__global__ void zero_hc_kernel() {
    int idx = blockIdx.x * blockDim.x + threadIdx.x;
    if (idx >= B_ * QH) return;
    g_c[idx] = 0.f;
    g_h[idx] = __float2bfloat16(0.f);
}

// ---------------- LSTM cell (after recurrent GEMM) ----------------
__global__ void lstm_cell_kernel(int t) {
    int idx = blockIdx.x * blockDim.x + threadIdx.x;   // exactly B_*QH threads
    int b = idx >> 10;
    int k = idx & 1023;
    size_t base = (size_t)b * G4H + 4 * (size_t)k;
    float4 gv = *(const float4*)(g_G + base);
    float4 xv = *(const float4*)(g_Xg + (size_t)t * B_ * G4H + base);
    float4 bv = *(const float4*)(g_bias + 4 * k);
    float vi = gv.x + xv.x + bv.x;
    float vf = gv.y + xv.y + bv.y;
    float vg = gv.z + xv.z + bv.z;
    float vo = gv.w + xv.w + bv.w;
    float ii = 1.f / (1.f + expf(-vi));
    float ff = 1.f / (1.f + expf(-vf));
    float gg = tanhf(vg);
    float oo = 1.f / (1.f + expf(-vo));
    float cn = ff * g_c[idx] + ii * gg;
    g_c[idx] = cn;
    g_h[idx] = __float2bfloat16(oo * tanhf(cn));
}

// ---------------- per-box score ----------------
__global__ void score_kernel() {
    int r = blockIdx.x;                 // 0..25599
    int b = r / MAXN_;
    const float* zr = g_Z  + (size_t)r * NBIG;
    const float* qr = g_qp + (size_t)b * NBIG;
    float p = 0.f;
    #pragma unroll
    for (int h = threadIdx.x; h < HID_; h += 128) {
        float2 z = *(const float2*)(zr + 2 * h);
        float2 q = *(const float2*)(qr + 2 * h);
        float2 m = *(const float2*)(g_mb + 2 * h);
        float z1 = z.x + q.x + m.x;
        float z2 = z.y + q.y + m.y;
        p += g_fw[h] * tanhf(z1) * (1.f / (1.f + expf(-z2)));
    }
    #pragma unroll
    for (int off = 16; off > 0; off >>= 1) p += __shfl_down_sync(0xffffffffu, p, off);
    __shared__ float red[4];
    if ((threadIdx.x & 31) == 0) red[threadIdx.x >> 5] = p;
    __syncthreads();
    if (threadIdx.x == 0) {
        float s = red[0] + red[1] + red[2] + red[3];
        g_wsi[r] = 1.f / (1.f + expf(-s));
    }
}

// ---------------- masked final sum (deterministic, no atomics) ----------------
__global__ void final_kernel(const int* __restrict__ index, float* __restrict__ out) {
    int b = blockIdx.x;
    int lim = index[b];
    float s = 0.f;
    for (int n = threadIdx.x; n < lim; n += 32) s += g_wsi[b * MAXN_ + n];
    #pragma unroll
    for (int off = 16; off > 0; off >>= 1) s += __shfl_down_sync(0xffffffffu, s, off);
    if (threadIdx.x == 0) out[b] = s;
}

// ---------------- launch ----------------
extern "C" void kernel_launch(void* const* d_in, const int* in_sizes, int n_in,
                              void* d_out, int out_size) {
    (void)in_sizes; (void)n_in; (void)out_size;
    const float* box_feats = (const float*)d_in[2];
    const float* q_feats   = (const float*)d_in[3];
    const int*   index     = (const int*)  d_in[5];
    const float* W_ih      = (const float*)d_in[6];
    const float* W_hh      = (const float*)d_in[7];
    const float* b_ih      = (const float*)d_in[8];
    const float* b_hh      = (const float*)d_in[9];
    const float* W_w       = (const float*)d_in[10];
    const float* W_b       = (const float*)d_in[11];
    const float* Wp_w      = (const float*)d_in[12];
    const float* Wp_b      = (const float*)d_in[13];
    const float* f_w       = (const float*)d_in[14];
    float* out = (float*)d_out;

    void* tmp;
    __nv_bfloat16 *Xbf_p, *Wih_p, *Whh_p, *h_p, *Wbox_p, *Wq_p, *box_p;
    float *Xg_p, *G_p, *qp_p, *Z_p;
    cudaGetSymbolAddress(&tmp, g_Xbf);  Xbf_p  = (__nv_bfloat16*)tmp;
    cudaGetSymbolAddress(&tmp, g_Wih);  Wih_p  = (__nv_bfloat16*)tmp;
    cudaGetSymbolAddress(&tmp, g_Whh);  Whh_p  = (__nv_bfloat16*)tmp;
    cudaGetSymbolAddress(&tmp, g_h);    h_p    = (__nv_bfloat16*)tmp;
    cudaGetSymbolAddress(&tmp, g_Wbox); Wbox_p = (__nv_bfloat16*)tmp;
    cudaGetSymbolAddress(&tmp, g_Wq);   Wq_p   = (__nv_bfloat16*)tmp;
    cudaGetSymbolAddress(&tmp, g_box);  box_p  = (__nv_bfloat16*)tmp;
    cudaGetSymbolAddress(&tmp, g_Xg);   Xg_p   = (float*)tmp;
    cudaGetSymbolAddress(&tmp, g_G);    G_p    = (float*)tmp;
    cudaGetSymbolAddress(&tmp, g_qp);   qp_p   = (float*)tmp;
    cudaGetSymbolAddress(&tmp, g_Z);    Z_p    = (float*)tmp;

    // -------- prep / conversion --------
    prep_x_kernel   <<<(T_ * B_ * E_PAD + 255) / 256, 256>>>(q_feats);
    prep_wih_kernel <<<(G4H * E_PAD + 255) / 256, 256>>>(W_ih);
    prep_whh_kernel <<<(G4H * QH) / 256, 256>>>(W_hh);
    prep_bias_kernel<<<G4H / 256, 256>>>(b_ih, b_hh);
    prep_wbox_kernel<<<(NBIG * ICNN) / 256, 256>>>(W_w, Wp_w);
    prep_wq_kernel  <<<(NBIG * QH) / 256, 256>>>(W_w, Wp_w);
    prep_small_kernel<<<((NBIG + HID_) + 255) / 256, 256>>>(W_b, Wp_b, f_w);
    conv_box_kernel <<<(ROWS_BIG * (size_t)ICNN) / 4 / 256, 256>>>(box_feats);
    zero_hc_kernel  <<<(B_ * QH) / 256, 256>>>();

    // -------- LSTM input projections: Xg[3584,4096] = Xbf * Wih^T --------
    gemm_bf16_nt<<<dim3(G4H / 128, (T_ * B_) / 128), 256>>>(Xbf_p, Wih_p, Xg_p, E_PAD, G4H);

    // -------- LSTM recurrence: 14 steps --------
    for (int t = 0; t < T_; t++) {
        gemm_bf16_nt<<<dim3(G4H / 128, B_ / 128), 256>>>(h_p, Whh_p, G_p, QH, G4H);
        lstm_cell_kernel<<<(B_ * QH) / 256, 256>>>(t);
    }

    // -------- question projections: qp[256,1024] = h * Wq^T --------
    gemm_bf16_nt<<<dim3(NBIG / 128, B_ / 128), 256>>>(h_p, Wq_p, qp_p, QH, NBIG);

    // -------- big box GEMM: Z[25600,1024] = box * Wbox^T --------
    gemm_bf16_nt<<<dim3(NBIG / 128, ROWS_BIG / 128), 256>>>(box_p, Wbox_p, Z_p, ICNN, NBIG);

    // -------- scores + masked ragged sum --------
    score_kernel<<<ROWS_BIG, 128>>>();
    final_kernel<<<B_, 32>>>(index, out);
}

// round 2
// speedup vs baseline: 1.0016x; 1.0016x over previous
#include <cuda_runtime.h>
#include <cuda_bf16.h>
#include <cstdint>
#include <cstddef>

// ---------------- problem constants ----------------
#define B_      256
#define T_      14
#define E_RAW   300
#define E_PAD   320        // pad K to multiple of 32
#define QH      1024
#define G4H     4096
#define ICNN    2048
#define MAXN_   100
#define HID_    512
#define ROWS_BIG (B_*MAXN_)   // 25600
#define NBIG     1024          // interleaved 2*HID

// ---------------- device scratch (static, allocation-free) ----------------
__device__ __nv_bfloat16 g_Xbf [(size_t)T_*B_*E_PAD];     // LSTM input, t-major, padded
__device__ __nv_bfloat16 g_Wih [(size_t)G4H*E_PAD];       // gate-interleaved rows, padded K
__device__ __nv_bfloat16 g_Whh [(size_t)G4H*QH];          // gate-interleaved rows
__device__ float         g_bias[G4H];                     // b_ih+b_hh, gate-interleaved
__device__ float         g_Xg  [(size_t)T_*B_*G4H];       // input projections (fp32)
__device__ float         g_G   [(size_t)B_*G4H];          // recurrent pre-gates per step
__device__ float         g_c   [(size_t)B_*QH];           // LSTM cell state
__device__ __nv_bfloat16 g_h   [(size_t)B_*QH];           // LSTM hidden (bf16)
__device__ __nv_bfloat16 g_Wbox[(size_t)NBIG*ICNN];       // rows 2h=W_w[h,:2048], 2h+1=Wp_w
__device__ __nv_bfloat16 g_Wq  [(size_t)NBIG*QH];         // rows 2h=W_w[h,2048:], 2h+1=Wp_w
__device__ float         g_mb  [NBIG];                    // interleaved W_b / Wp_b
__device__ float         g_fw  [HID_];
__device__ float         g_qp  [(size_t)B_*NBIG];         // question projections
__device__ __nv_bfloat16 g_box [(size_t)ROWS_BIG*ICNN];   // box feats bf16
__device__ float         g_Z   [(size_t)ROWS_BIG*NBIG];   // box-part pre-activations
__device__ float         g_wsi [ROWS_BIG];

// ---------------- mma.sync m16n8k16 bf16 ----------------
__device__ __forceinline__ void mma16816(float acc[4], const uint32_t a[4], const uint32_t b[2]) {
    asm volatile(
        "mma.sync.aligned.m16n8k16.row.col.f32.bf16.bf16.f32 "
        "{%0,%1,%2,%3}, {%4,%5,%6,%7}, {%8,%9}, {%0,%1,%2,%3};\n"
        : "+f"(acc[0]), "+f"(acc[1]), "+f"(acc[2]), "+f"(acc[3])
        : "r"(a[0]), "r"(a[1]), "r"(a[2]), "r"(a[3]), "r"(b[0]), "r"(b[1]));
}

// C[M,N] (fp32) = A[M,K] * B[N,K]^T, bf16 inputs, row-major, K%32==0, M%128==0, N%128==0.
// Tile 128x128x32, 256 threads (8 warps, 2x4), warp tile 64x32.
__global__ __launch_bounds__(256) void gemm_bf16_nt(
    const __nv_bfloat16* __restrict__ A,
    const __nv_bfloat16* __restrict__ B,
    float* __restrict__ C,
    int K, int N)
{
    __shared__ __align__(16) __nv_bfloat16 sA[128][40];   // 32 + 8 pad (conflict-free)
    __shared__ __align__(16) __nv_bfloat16 sB[128][40];

    const int tid  = threadIdx.x;
    const int warp = tid >> 5;
    const int lane = tid & 31;
    const int wm   = warp >> 2;       // 0..1
    const int wn   = warp & 3;        // 0..3
    const int g    = lane >> 2;       // 0..7
    const int tt   = lane & 3;        // 0..3

    const size_t m0 = (size_t)blockIdx.y * 128;
    const size_t n0 = (size_t)blockIdx.x * 128;

    const int r0  = tid >> 2;         // rows 0..63
    const int ch0 = tid & 3;          // 4 x uint4 (8 bf16) chunks per 32-wide row
    const int r1  = r0 + 64;

    const __nv_bfloat16* Ag0 = A + (m0 + r0) * (size_t)K + ch0 * 8;
    const __nv_bfloat16* Ag1 = A + (m0 + r1) * (size_t)K + ch0 * 8;
    const __nv_bfloat16* Bg0 = B + (n0 + r0) * (size_t)K + ch0 * 8;
    const __nv_bfloat16* Bg1 = B + (n0 + r1) * (size_t)K + ch0 * 8;

    float acc[4][4][4];
    #pragma unroll
    for (int mi = 0; mi < 4; mi++)
        #pragma unroll
        for (int ni = 0; ni < 4; ni++)
            #pragma unroll
            for (int e = 0; e < 4; e++) acc[mi][ni][e] = 0.f;

    for (int k0 = 0; k0 < K; k0 += 32) {
        uint4 av0 = *(const uint4*)(Ag0 + k0);
        uint4 av1 = *(const uint4*)(Ag1 + k0);
        uint4 bv0 = *(const uint4*)(Bg0 + k0);
        uint4 bv1 = *(const uint4*)(Bg1 + k0);
        __syncthreads();
        *(uint4*)&sA[r0][ch0 * 8] = av0;
        *(uint4*)&sA[r1][ch0 * 8] = av1;
        *(uint4*)&sB[r0][ch0 * 8] = bv0;
        *(uint4*)&sB[r1][ch0 * 8] = bv1;
        __syncthreads();

        #pragma unroll
        for (int kk = 0; kk < 2; kk++) {
            const int kb = kk * 16 + tt * 2;
            uint32_t af[4][4];
            uint32_t bfr[4][2];
            #pragma unroll
            for (int mi = 0; mi < 4; mi++) {
                const int r = wm * 64 + mi * 16;
                af[mi][0] = *(const uint32_t*)&sA[r + g    ][kb];
                af[mi][1] = *(const uint32_t*)&sA[r + 8 + g][kb];
                af[mi][2] = *(const uint32_t*)&sA[r + g    ][kb + 8];
                af[mi][3] = *(const uint32_t*)&sA[r + 8 + g][kb + 8];
            }
            #pragma unroll
            for (int ni = 0; ni < 4; ni++) {
                const int cc = wn * 32 + ni * 8;
                bfr[ni][0] = *(const uint32_t*)&sB[cc + g][kb];
                bfr[ni][1] = *(const uint32_t*)&sB[cc + g][kb + 8];
            }
            #pragma unroll
            for (int mi = 0; mi < 4; mi++)
                #pragma unroll
                for (int ni = 0; ni < 4; ni++)
                    mma16816(acc[mi][ni], af[mi], bfr[ni]);
        }
    }

    #pragma unroll
    for (int mi = 0; mi < 4; mi++) {
        const size_t row = m0 + wm * 64 + mi * 16 + g;
        #pragma unroll
        for (int ni = 0; ni < 4; ni++) {
            const size_t col = n0 + wn * 32 + ni * 8 + tt * 2;
            float2 v01 = make_float2(acc[mi][ni][0], acc[mi][ni][1]);
            float2 v23 = make_float2(acc[mi][ni][2], acc[mi][ni][3]);
            *(float2*)&C[row       * (size_t)N + col] = v01;
            *(float2*)&C[(row + 8) * (size_t)N + col] = v23;
        }
    }
}

// ---------------- prep kernels ----------------
// gate-interleaved source row: output row j -> gate (j&3), hidden (j>>2)
__device__ __forceinline__ int lstm_src_row(int j) { return (j & 3) * QH + (j >> 2); }

__global__ void prep_x_kernel(const float* __restrict__ q_feats) {
    int idx = blockIdx.x * blockDim.x + threadIdx.x;
    if (idx >= T_ * B_ * E_PAD) return;
    int r = idx / E_PAD, e = idx % E_PAD;
    int t = r >> 8, b = r & 255;                      // r = t*256 + b
    float v = (e < E_RAW) ? q_feats[((size_t)b * T_ + t) * E_RAW + e] : 0.f;
    g_Xbf[idx] = __float2bfloat16(v);
}

__global__ void prep_wih_kernel(const float* __restrict__ W_ih) {
    int idx = blockIdx.x * blockDim.x + threadIdx.x;
    if (idx >= G4H * E_PAD) return;
    int j = idx / E_PAD, e = idx % E_PAD;
    int src = lstm_src_row(j);
    float v = (e < E_RAW) ? W_ih[(size_t)src * E_RAW + e] : 0.f;
    g_Wih[idx] = __float2bfloat16(v);
}

__global__ void prep_whh_kernel(const float* __restrict__ W_hh) {
    int idx = blockIdx.x * blockDim.x + threadIdx.x;
    if (idx >= G4H * QH) return;
    int j = idx >> 10, e = idx & 1023;
    int src = lstm_src_row(j);
    g_Whh[idx] = __float2bfloat16(W_hh[(size_t)src * QH + e]);
}

__global__ void prep_bias_kernel(const float* __restrict__ b_ih, const float* __restrict__ b_hh) {
    int j = blockIdx.x * blockDim.x + threadIdx.x;
    if (j >= G4H) return;
    int src = lstm_src_row(j);
    g_bias[j] = b_ih[src] + b_hh[src];
}

__global__ void prep_wbox_kernel(const float* __restrict__ W_w, const float* __restrict__ Wp_w) {
    int idx = blockIdx.x * blockDim.x + threadIdx.x;
    if (idx >= NBIG * ICNN) return;
    int j = idx >> 11, cc = idx & 2047;
    int h = j >> 1;
    const float* s = (j & 1) ? Wp_w : W_w;
    g_Wbox[idx] = __float2bfloat16(s[(size_t)h * (ICNN + QH) + cc]);
}

__global__ void prep_wq_kernel(const float* __restrict__ W_w, const float* __restrict__ Wp_w) {
    int idx = blockIdx.x * blockDim.x + threadIdx.x;
    if (idx >= NBIG * QH) return;
    int j = idx >> 10, cc = idx & 1023;
    int h = j >> 1;
    const float* s = (j & 1) ? Wp_w : W_w;
    g_Wq[idx] = __float2bfloat16(s[(size_t)h * (ICNN + QH) + ICNN + cc]);
}

__global__ void prep_small_kernel(const float* __restrict__ W_b, const float* __restrict__ Wp_b,
                                  const float* __restrict__ f_w) {
    int idx = blockIdx.x * blockDim.x + threadIdx.x;
    if (idx < NBIG) {
        g_mb[idx] = (idx & 1) ? Wp_b[idx >> 1] : W_b[idx >> 1];
    } else if (idx < NBIG + HID_) {
        g_fw[idx - NBIG] = f_w[idx - NBIG];
    }
}

__global__ void conv_box_kernel(const float* __restrict__ box) {
    size_t i = ((size_t)blockIdx.x * blockDim.x + threadIdx.x) * 4;   // grid sized exactly
    float4 v = *(const float4*)(box + i);
    __nv_bfloat162 p0 = __floats2bfloat162_rn(v.x, v.y);
    __nv_bfloat162 p1 = __floats2bfloat162_rn(v.z, v.w);
    *(__nv_bfloat162*)(g_box + i)     = p0;
    *(__nv_bfloat162*)(g_box + i + 2) = p1;
}

__global__ void zero_hc_kernel() {
    int idx = blockIdx.x * blockDim.x + threadIdx.x;
    if (idx >= B_ * QH) return;
    g_c[idx] = 0.f;
    g_h[idx] = __float2bfloat16(0.f);
}

// ---------------- LSTM cell (after recurrent GEMM) ----------------
__global__ void lstm_cell_kernel(int t) {
    int idx = blockIdx.x * blockDim.x + threadIdx.x;   // exactly B_*QH threads
    int b = idx >> 10;
    int k = idx & 1023;
    size_t base = (size_t)b * G4H + 4 * (size_t)k;
    float4 gv = *(const float4*)(g_G + base);
    float4 xv = *(const float4*)(g_Xg + (size_t)t * B_ * G4H + base);
    float4 bv = *(const float4*)(g_bias + 4 * k);
    float vi = gv.x + xv.x + bv.x;
    float vf = gv.y + xv.y + bv.y;
    float vg = gv.z + xv.z + bv.z;
    float vo = gv.w + xv.w + bv.w;
    float ii = 1.f / (1.f + expf(-vi));
    float ff = 1.f / (1.f + expf(-vf));
    float gg = tanhf(vg);
    float oo = 1.f / (1.f + expf(-vo));
    float cn = ff * g_c[idx] + ii * gg;
    g_c[idx] = cn;
    g_h[idx] = __float2bfloat16(oo * tanhf(cn));
}

// ---------------- per-box score ----------------
__global__ void score_kernel() {
    int r = blockIdx.x;                 // 0..25599
    int b = r / MAXN_;
    const float* zr = g_Z  + (size_t)r * NBIG;
    const float* qr = g_qp + (size_t)b * NBIG;
    float p = 0.f;
    #pragma unroll
    for (int h = threadIdx.x; h < HID_; h += 128) {
        float2 z = *(const float2*)(zr + 2 * h);
        float2 q = *(const float2*)(qr + 2 * h);
        float2 m = *(const float2*)(g_mb + 2 * h);
        float z1 = z.x + q.x + m.x;
        float z2 = z.y + q.y + m.y;
        p += g_fw[h] * tanhf(z1) * (1.f / (1.f + expf(-z2)));
    }
    #pragma unroll
    for (int off = 16; off > 0; off >>= 1) p += __shfl_down_sync(0xffffffffu, p, off);
    __shared__ float red[4];
    if ((threadIdx.x & 31) == 0) red[threadIdx.x >> 5] = p;
    __syncthreads();
    if (threadIdx.x == 0) {
        float s = red[0] + red[1] + red[2] + red[3];
        g_wsi[r] = 1.f / (1.f + expf(-s));
    }
}

// ---------------- masked final sum (deterministic, no atomics) ----------------
__global__ void final_kernel(const int* __restrict__ index, float* __restrict__ out) {
    int b = blockIdx.x;
    int lim = index[b];
    float s = 0.f;
    for (int n = threadIdx.x; n < lim; n += 32) s += g_wsi[b * MAXN_ + n];
    #pragma unroll
    for (int off = 16; off > 0; off >>= 1) s += __shfl_down_sync(0xffffffffu, s, off);
    if (threadIdx.x == 0) out[b] = s;
}

// ---------------- launch ----------------
extern "C" void kernel_launch(void* const* d_in, const int* in_sizes, int n_in,
                              void* d_out, int out_size) {
    (void)in_sizes; (void)n_in; (void)out_size;
    const float* box_feats = (const float*)d_in[2];
    const float* q_feats   = (const float*)d_in[3];
    const int*   index     = (const int*)  d_in[5];
    const float* W_ih      = (const float*)d_in[6];
    const float* W_hh      = (const float*)d_in[7];
    const float* b_ih      = (const float*)d_in[8];
    const float* b_hh      = (const float*)d_in[9];
    const float* W_w       = (const float*)d_in[10];
    const float* W_b       = (const float*)d_in[11];
    const float* Wp_w      = (const float*)d_in[12];
    const float* Wp_b      = (const float*)d_in[13];
    const float* f_w       = (const float*)d_in[14];
    float* out = (float*)d_out;

    void* tmp;
    __nv_bfloat16 *Xbf_p, *Wih_p, *Whh_p, *h_p, *Wbox_p, *Wq_p, *box_p;
    float *Xg_p, *G_p, *qp_p, *Z_p;
    cudaGetSymbolAddress(&tmp, g_Xbf);  Xbf_p  = (__nv_bfloat16*)tmp;
    cudaGetSymbolAddress(&tmp, g_Wih);  Wih_p  = (__nv_bfloat16*)tmp;
    cudaGetSymbolAddress(&tmp, g_Whh);  Whh_p  = (__nv_bfloat16*)tmp;
    cudaGetSymbolAddress(&tmp, g_h);    h_p    = (__nv_bfloat16*)tmp;
    cudaGetSymbolAddress(&tmp, g_Wbox); Wbox_p = (__nv_bfloat16*)tmp;
    cudaGetSymbolAddress(&tmp, g_Wq);   Wq_p   = (__nv_bfloat16*)tmp;
    cudaGetSymbolAddress(&tmp, g_box);  box_p  = (__nv_bfloat16*)tmp;
    cudaGetSymbolAddress(&tmp, g_Xg);   Xg_p   = (float*)tmp;
    cudaGetSymbolAddress(&tmp, g_G);    G_p    = (float*)tmp;
    cudaGetSymbolAddress(&tmp, g_qp);   qp_p   = (float*)tmp;
    cudaGetSymbolAddress(&tmp, g_Z);    Z_p    = (float*)tmp;

    // -------- prep / conversion --------
    prep_x_kernel   <<<(T_ * B_ * E_PAD + 255) / 256, 256>>>(q_feats);
    prep_wih_kernel <<<(G4H * E_PAD + 255) / 256, 256>>>(W_ih);
    prep_whh_kernel <<<(G4H * QH) / 256, 256>>>(W_hh);
    prep_bias_kernel<<<G4H / 256, 256>>>(b_ih, b_hh);
    prep_wbox_kernel<<<(NBIG * ICNN) / 256, 256>>>(W_w, Wp_w);
    prep_wq_kernel  <<<(NBIG * QH) / 256, 256>>>(W_w, Wp_w);
    prep_small_kernel<<<((NBIG + HID_) + 255) / 256, 256>>>(W_b, Wp_b, f_w);
    conv_box_kernel <<<(ROWS_BIG * (size_t)ICNN) / 4 / 256, 256>>>(box_feats);
    zero_hc_kernel  <<<(B_ * QH) / 256, 256>>>();

    // -------- LSTM input projections: Xg[3584,4096] = Xbf * Wih^T --------
    gemm_bf16_nt<<<dim3(G4H / 128, (T_ * B_) / 128), 256>>>(Xbf_p, Wih_p, Xg_p, E_PAD, G4H);

    // -------- LSTM recurrence: 14 steps --------
    for (int t = 0; t < T_; t++) {
        gemm_bf16_nt<<<dim3(G4H / 128, B_ / 128), 256>>>(h_p, Whh_p, G_p, QH, G4H);
        lstm_cell_kernel<<<(B_ * QH) / 256, 256>>>(t);
    }

    // -------- question projections: qp[256,1024] = h * Wq^T --------
    gemm_bf16_nt<<<dim3(NBIG / 128, B_ / 128), 256>>>(h_p, Wq_p, qp_p, QH, NBIG);

    // -------- big box GEMM: Z[25600,1024] = box * Wbox^T --------
    gemm_bf16_nt<<<dim3(NBIG / 128, ROWS_BIG / 128), 256>>>(box_p, Wbox_p, Z_p, ICNN, NBIG);

    // -------- scores + masked ragged sum --------
    score_kernel<<<ROWS_BIG, 128>>>();
    final_kernel<<<B_, 32>>>(index, out);
}

// round 3
// speedup vs baseline: 1.2527x; 1.2506x over previous
#include <cuda_runtime.h>
#include <cuda_bf16.h>
#include <cstdint>
#include <cstddef>

// ---------------- problem constants ----------------
#define B_      256
#define T_      14
#define E_RAW   300
#define E_PAD   320        // pad K to multiple of 32
#define QH      1024
#define G4H     4096
#define ICNN    2048
#define MAXN_   100
#define HID_    512
#define ROWS_BIG (B_*MAXN_)   // 25600
#define NBIG     1024          // interleaved 2*HID

// ---------------- device scratch (static, allocation-free) ----------------
__device__ __align__(16) __nv_bfloat16 g_Xbf [(size_t)T_*B_*E_PAD];
__device__ __align__(16) __nv_bfloat16 g_Wih [(size_t)G4H*E_PAD];
__device__ __align__(16) __nv_bfloat16 g_Whh [(size_t)G4H*QH];
__device__ __align__(16) float         g_bias[G4H];
__device__ __align__(16) float         g_Xg  [(size_t)T_*B_*G4H];
__device__ __align__(16) __nv_bfloat16 g_h   [(size_t)B_*QH];
__device__ __align__(16) __nv_bfloat16 g_Wbox[(size_t)NBIG*ICNN];
__device__ __align__(16) __nv_bfloat16 g_Wq  [(size_t)NBIG*QH];
__device__ __align__(16) float         g_mb  [NBIG];
__device__ __align__(16) float         g_fw  [HID_];
__device__ __align__(16) float         g_qp  [(size_t)B_*NBIG];
__device__ __align__(16) __nv_bfloat16 g_box [(size_t)ROWS_BIG*ICNN];
__device__ __align__(16) float         g_Z   [(size_t)ROWS_BIG*NBIG];
__device__ __align__(16) float         g_wsi [ROWS_BIG];
__device__ unsigned g_bar;

// ---------------- small helpers ----------------
__device__ __forceinline__ void mma16816(float acc[4], const uint32_t a[4], const uint32_t b[2]) {
    asm volatile(
        "mma.sync.aligned.m16n8k16.row.col.f32.bf16.bf16.f32 "
        "{%0,%1,%2,%3}, {%4,%5,%6,%7}, {%8,%9}, {%0,%1,%2,%3};\n"
        : "+f"(acc[0]), "+f"(acc[1]), "+f"(acc[2]), "+f"(acc[3])
        : "r"(a[0]), "r"(a[1]), "r"(a[2]), "r"(a[3]), "r"(b[0]), "r"(b[1]));
}

__device__ __forceinline__ void cp_async16(void* smem, const void* gmem) {
    uint32_t sa = (uint32_t)__cvta_generic_to_shared(smem);
    asm volatile("cp.async.cg.shared.global [%0], [%1], 16;\n" :: "r"(sa), "l"(gmem));
}
#define CP_COMMIT() asm volatile("cp.async.commit_group;\n" ::)
#define CP_WAIT0()  asm volatile("cp.async.wait_group 0;\n" ::)

__device__ __forceinline__ float sigf(float x) { return 1.f / (1.f + __expf(-x)); }

// ============================================================================
// Generic GEMM: C[M,N] fp32 = A[M,K]*B[N,K]^T, bf16, 128x128x32 tiles,
// 2-stage cp.async pipeline, 8 warps (2x4), warp tile 64x32.
// M%128==0, N%128==0, K%32==0.
// ============================================================================
__global__ __launch_bounds__(256, 2) void gemm_bf16_nt(
    const __nv_bfloat16* __restrict__ A,
    const __nv_bfloat16* __restrict__ B,
    float* __restrict__ C,
    int K, int N)
{
    __shared__ __align__(16) __nv_bfloat16 sA[2][128][40];
    __shared__ __align__(16) __nv_bfloat16 sB[2][128][40];

    const int tid  = threadIdx.x;
    const int warp = tid >> 5;
    const int lane = tid & 31;
    const int wm   = warp >> 2;       // 0..1
    const int wn   = warp & 3;        // 0..3
    const int g    = lane >> 2;       // 0..7
    const int tt   = lane & 3;        // 0..3

    const size_t m0 = (size_t)blockIdx.y * 128;
    const size_t n0 = (size_t)blockIdx.x * 128;

    const int r0  = tid >> 2;         // 0..63
    const int ch0 = tid & 3;
    const int r1  = r0 + 64;

    const __nv_bfloat16* Ag0 = A + (m0 + r0) * (size_t)K + ch0 * 8;
    const __nv_bfloat16* Ag1 = A + (m0 + r1) * (size_t)K + ch0 * 8;
    const __nv_bfloat16* Bg0 = B + (n0 + r0) * (size_t)K + ch0 * 8;
    const __nv_bfloat16* Bg1 = B + (n0 + r1) * (size_t)K + ch0 * 8;

    float acc[4][4][4];
    #pragma unroll
    for (int mi = 0; mi < 4; mi++)
        #pragma unroll
        for (int ni = 0; ni < 4; ni++)
            #pragma unroll
            for (int e = 0; e < 4; e++) acc[mi][ni][e] = 0.f;

    const int nk = K / 32;
    // prefetch stage 0
    cp_async16(&sA[0][r0][ch0 * 8], Ag0);
    cp_async16(&sA[0][r1][ch0 * 8], Ag1);
    cp_async16(&sB[0][r0][ch0 * 8], Bg0);
    cp_async16(&sB[0][r1][ch0 * 8], Bg1);
    CP_COMMIT();

    for (int k = 0; k < nk; k++) {
        CP_WAIT0();
        __syncthreads();
        if (k + 1 < nk) {
            const int s  = (k + 1) & 1;
            const int ko = (k + 1) * 32;
            cp_async16(&sA[s][r0][ch0 * 8], Ag0 + ko);
            cp_async16(&sA[s][r1][ch0 * 8], Ag1 + ko);
            cp_async16(&sB[s][r0][ch0 * 8], Bg0 + ko);
            cp_async16(&sB[s][r1][ch0 * 8], Bg1 + ko);
        }
        CP_COMMIT();

        const int st = k & 1;
        #pragma unroll
        for (int kk = 0; kk < 2; kk++) {
            const int kb = kk * 16 + tt * 2;
            uint32_t af[4][4];
            uint32_t bfr[4][2];
            #pragma unroll
            for (int mi = 0; mi < 4; mi++) {
                const int r = wm * 64 + mi * 16;
                af[mi][0] = *(const uint32_t*)&sA[st][r + g    ][kb];
                af[mi][1] = *(const uint32_t*)&sA[st][r + 8 + g][kb];
                af[mi][2] = *(const uint32_t*)&sA[st][r + g    ][kb + 8];
                af[mi][3] = *(const uint32_t*)&sA[st][r + 8 + g][kb + 8];
            }
            #pragma unroll
            for (int ni = 0; ni < 4; ni++) {
                const int cc = wn * 32 + ni * 8;
                bfr[ni][0] = *(const uint32_t*)&sB[st][cc + g][kb];
                bfr[ni][1] = *(const uint32_t*)&sB[st][cc + g][kb + 8];
            }
            #pragma unroll
            for (int mi = 0; mi < 4; mi++)
                #pragma unroll
                for (int ni = 0; ni < 4; ni++)
                    mma16816(acc[mi][ni], af[mi], bfr[ni]);
        }
    }

    #pragma unroll
    for (int mi = 0; mi < 4; mi++) {
        const size_t row = m0 + wm * 64 + mi * 16 + g;
        #pragma unroll
        for (int ni = 0; ni < 4; ni++) {
            const size_t col = n0 + wn * 32 + ni * 8 + tt * 2;
            *(float2*)&C[row       * (size_t)N + col] = make_float2(acc[mi][ni][0], acc[mi][ni][1]);
            *(float2*)&C[(row + 8) * (size_t)N + col] = make_float2(acc[mi][ni][2], acc[mi][ni][3]);
        }
    }
}

// ============================================================================
// Persistent fused LSTM: 14 steps in one launch.
// Grid (32,4) = 128 blocks (all co-resident on 148 SMs), tile 64 rows x 128 cols,
// 8 warps (2x4), warp tile 32x32. Cell state c lives in registers; h (bf16)
// round-trips through global between steps with an atomic grid barrier.
// Gate-interleaved columns: col 4k+gate; even-tt lanes hold (i,f), odd (g,o).
// ============================================================================
__global__ __launch_bounds__(256) void lstm_persistent_kernel()
{
    __shared__ __align__(16) __nv_bfloat16 sA[2][64][40];
    __shared__ __align__(16) __nv_bfloat16 sB[2][128][40];

    const int tid  = threadIdx.x;
    const int warp = tid >> 5;
    const int lane = tid & 31;
    const int wm   = warp >> 2;       // 0..1 (32 rows each)
    const int wn   = warp & 3;        // 0..3 (32 cols each)
    const int g    = lane >> 2;
    const int tt   = lane & 3;

    const int m0 = blockIdx.y * 64;    // rows (batch)
    const int n0 = blockIdx.x * 128;   // cols (gate-interleaved)

    const int rA  = tid >> 2;          // 0..63
    const int ch0 = tid & 3;
    const int rB1 = rA + 64;

    const __nv_bfloat16* Ag  = g_h   + (size_t)(m0 + rA)  * QH + ch0 * 8;
    const __nv_bfloat16* Bg0 = g_Whh + (size_t)(n0 + rA)  * QH + ch0 * 8;
    const __nv_bfloat16* Bg1 = g_Whh + (size_t)(n0 + rB1) * QH + ch0 * 8;

    // bias preload (cols fixed across steps)
    float bias0[4], bias1[4];
    #pragma unroll
    for (int ni = 0; ni < 4; ni++) {
        const int c = n0 + wn * 32 + ni * 8 + 2 * tt;
        bias0[ni] = g_bias[c];
        bias1[ni] = g_bias[c + 1];
    }

    float creg[2][4][2];
    #pragma unroll
    for (int mi = 0; mi < 2; mi++)
        #pragma unroll
        for (int ni = 0; ni < 4; ni++) { creg[mi][ni][0] = 0.f; creg[mi][ni][1] = 0.f; }

    for (int t = 0; t < T_; t++) {
        float acc[2][4][4];
        #pragma unroll
        for (int mi = 0; mi < 2; mi++)
            #pragma unroll
            for (int ni = 0; ni < 4; ni++)
                #pragma unroll
                for (int e = 0; e < 4; e++) acc[mi][ni][e] = 0.f;

        if (t > 0) {
            // K=1024, 32 k-iters, 2-stage cp.async
            cp_async16(&sA[0][rA][ch0 * 8], Ag);
            cp_async16(&sB[0][rA][ch0 * 8], Bg0);
            cp_async16(&sB[0][rB1][ch0 * 8], Bg1);
            CP_COMMIT();
            for (int k = 0; k < 32; k++) {
                CP_WAIT0();
                __syncthreads();
                if (k < 31) {
                    const int s  = (k + 1) & 1;
                    const int ko = (k + 1) * 32;
                    cp_async16(&sA[s][rA][ch0 * 8], Ag + ko);
                    cp_async16(&sB[s][rA][ch0 * 8], Bg0 + ko);
                    cp_async16(&sB[s][rB1][ch0 * 8], Bg1 + ko);
                }
                CP_COMMIT();

                const int st = k & 1;
                #pragma unroll
                for (int kk = 0; kk < 2; kk++) {
                    const int kb = kk * 16 + tt * 2;
                    uint32_t af[2][4];
                    uint32_t bfr[4][2];
                    #pragma unroll
                    for (int mi = 0; mi < 2; mi++) {
                        const int r = wm * 32 + mi * 16;
                        af[mi][0] = *(const uint32_t*)&sA[st][r + g    ][kb];
                        af[mi][1] = *(const uint32_t*)&sA[st][r + 8 + g][kb];
                        af[mi][2] = *(const uint32_t*)&sA[st][r + g    ][kb + 8];
                        af[mi][3] = *(const uint32_t*)&sA[st][r + 8 + g][kb + 8];
                    }
                    #pragma unroll
                    for (int ni = 0; ni < 4; ni++) {
                        const int cc = wn * 32 + ni * 8;
                        bfr[ni][0] = *(const uint32_t*)&sB[st][cc + g][kb];
                        bfr[ni][1] = *(const uint32_t*)&sB[st][cc + g][kb + 8];
                    }
                    #pragma unroll
                    for (int mi = 0; mi < 2; mi++)
                        #pragma unroll
                        for (int ni = 0; ni < 4; ni++)
                            mma16816(acc[mi][ni], af[mi], bfr[ni]);
                }
            }
        }

        // -------- cell epilogue --------
        const float* xg = g_Xg + (size_t)(t * B_ + m0) * G4H;
        #pragma unroll
        for (int mi = 0; mi < 2; mi++) {
            #pragma unroll
            for (int ro = 0; ro < 2; ro++) {
                const int rowl = wm * 32 + mi * 16 + g + ro * 8;
                #pragma unroll
                for (int ni = 0; ni < 4; ni++) {
                    const int cl = wn * 32 + ni * 8 + 2 * tt;
                    const float2 x = *(const float2*)(xg + (size_t)rowl * G4H + n0 + cl);
                    const float v0 = acc[mi][ni][ro * 2 + 0] + x.x + bias0[ni];
                    const float v1 = acc[mi][ni][ro * 2 + 1] + x.y + bias1[ni];
                    const float p0 = __shfl_xor_sync(0xffffffffu, v0, 1);
                    const float p1 = __shfl_xor_sync(0xffffffffu, v1, 1);
                    if ((tt & 1) == 0) {
                        const float ii = sigf(v0);
                        const float ff = sigf(v1);
                        const float gg = tanhf(p0);
                        const float oo = sigf(p1);
                        const float cn = ff * creg[mi][ni][ro] + ii * gg;
                        creg[mi][ni][ro] = cn;
                        const int kg = (n0 + cl) >> 2;   // hidden index
                        g_h[(size_t)(m0 + rowl) * QH + kg] = __float2bfloat16(oo * tanhf(cn));
                    }
                }
            }
        }

        // -------- grid barrier between steps --------
        if (t < T_ - 1) {
            __threadfence();
            __syncthreads();
            if (tid == 0) {
                atomicAdd(&g_bar, 1u);
                const unsigned target = 128u * (unsigned)(t + 1);
                while (atomicAdd(&g_bar, 0u) < target) { __nanosleep(64); }
            }
            __syncthreads();
        }
    }
}

// ---------------- prep kernels ----------------
__device__ __forceinline__ int lstm_src_row(int j) { return (j & 3) * QH + (j >> 2); }

__global__ void prep_x_kernel(const float* __restrict__ q_feats) {
    int idx = blockIdx.x * blockDim.x + threadIdx.x;
    if (idx >= T_ * B_ * E_PAD) return;
    int r = idx / E_PAD, e = idx % E_PAD;
    int t = r >> 8, b = r & 255;
    float v = (e < E_RAW) ? q_feats[((size_t)b * T_ + t) * E_RAW + e] : 0.f;
    g_Xbf[idx] = __float2bfloat16(v);
}

__global__ void prep_wih_kernel(const float* __restrict__ W_ih) {
    int idx = blockIdx.x * blockDim.x + threadIdx.x;
    if (idx >= G4H * E_PAD) return;
    int j = idx / E_PAD, e = idx % E_PAD;
    int src = lstm_src_row(j);
    float v = (e < E_RAW) ? W_ih[(size_t)src * E_RAW + e] : 0.f;
    g_Wih[idx] = __float2bfloat16(v);
}

__global__ void prep_whh_kernel(const float* __restrict__ W_hh) {
    int idx = blockIdx.x * blockDim.x + threadIdx.x;
    if (idx >= G4H * QH) return;
    int j = idx >> 10, e = idx & 1023;
    int src = lstm_src_row(j);
    g_Whh[idx] = __float2bfloat16(W_hh[(size_t)src * QH + e]);
}

__global__ void prep_bias_kernel(const float* __restrict__ b_ih, const float* __restrict__ b_hh) {
    int j = blockIdx.x * blockDim.x + threadIdx.x;
    if (j == 0) g_bar = 0u;                 // reset grid barrier each replay
    if (j >= G4H) return;
    int src = lstm_src_row(j);
    g_bias[j] = b_ih[src] + b_hh[src];
}

__global__ void prep_wbox_kernel(const float* __restrict__ W_w, const float* __restrict__ Wp_w) {
    int idx = blockIdx.x * blockDim.x + threadIdx.x;
    if (idx >= NBIG * ICNN) return;
    int j = idx >> 11, cc = idx & 2047;
    int h = j >> 1;
    const float* s = (j & 1) ? Wp_w : W_w;
    g_Wbox[idx] = __float2bfloat16(s[(size_t)h * (ICNN + QH) + cc]);
}

__global__ void prep_wq_kernel(const float* __restrict__ W_w, const float* __restrict__ Wp_w) {
    int idx = blockIdx.x * blockDim.x + threadIdx.x;
    if (idx >= NBIG * QH) return;
    int j = idx >> 10, cc = idx & 1023;
    int h = j >> 1;
    const float* s = (j & 1) ? Wp_w : W_w;
    g_Wq[idx] = __float2bfloat16(s[(size_t)h * (ICNN + QH) + ICNN + cc]);
}

__global__ void prep_small_kernel(const float* __restrict__ W_b, const float* __restrict__ Wp_b,
                                  const float* __restrict__ f_w) {
    int idx = blockIdx.x * blockDim.x + threadIdx.x;
    if (idx < NBIG) {
        g_mb[idx] = (idx & 1) ? Wp_b[idx >> 1] : W_b[idx >> 1];
    } else if (idx < NBIG + HID_) {
        g_fw[idx - NBIG] = f_w[idx - NBIG];
    }
}

__global__ void conv_box_kernel(const float* __restrict__ box) {
    size_t i = ((size_t)blockIdx.x * blockDim.x + threadIdx.x) * 4;
    float4 v = *(const float4*)(box + i);
    *(__nv_bfloat162*)(g_box + i)     = __floats2bfloat162_rn(v.x, v.y);
    *(__nv_bfloat162*)(g_box + i + 2) = __floats2bfloat162_rn(v.z, v.w);
}

// ---------------- per-box score ----------------
__global__ void score_kernel() {
    int r = blockIdx.x;
    int b = r / MAXN_;
    const float* zr = g_Z  + (size_t)r * NBIG;
    const float* qr = g_qp + (size_t)b * NBIG;
    float p = 0.f;
    #pragma unroll
    for (int h = threadIdx.x; h < HID_; h += 128) {
        float2 z = *(const float2*)(zr + 2 * h);
        float2 q = *(const float2*)(qr + 2 * h);
        float2 m = *(const float2*)(g_mb + 2 * h);
        float z1 = z.x + q.x + m.x;
        float z2 = z.y + q.y + m.y;
        p += g_fw[h] * tanhf(z1) * sigf(z2);
    }
    #pragma unroll
    for (int off = 16; off > 0; off >>= 1) p += __shfl_down_sync(0xffffffffu, p, off);
    __shared__ float red[4];
    if ((threadIdx.x & 31) == 0) red[threadIdx.x >> 5] = p;
    __syncthreads();
    if (threadIdx.x == 0) {
        float s = red[0] + red[1] + red[2] + red[3];
        g_wsi[r] = sigf(s);
    }
}

// ---------------- masked final sum (deterministic, no atomics) ----------------
__global__ void final_kernel(const int* __restrict__ index, float* __restrict__ out) {
    int b = blockIdx.x;
    int lim = index[b];
    float s = 0.f;
    for (int n = threadIdx.x; n < lim; n += 32) s += g_wsi[b * MAXN_ + n];
    #pragma unroll
    for (int off = 16; off > 0; off >>= 1) s += __shfl_down_sync(0xffffffffu, s, off);
    if (threadIdx.x == 0) out[b] = s;
}

// ---------------- launch ----------------
extern "C" void kernel_launch(void* const* d_in, const int* in_sizes, int n_in,
                              void* d_out, int out_size) {
    (void)in_sizes; (void)n_in; (void)out_size;
    const float* box_feats = (const float*)d_in[2];
    const float* q_feats   = (const float*)d_in[3];
    const int*   index     = (const int*)  d_in[5];
    const float* W_ih      = (const float*)d_in[6];
    const float* W_hh      = (const float*)d_in[7];
    const float* b_ih      = (const float*)d_in[8];
    const float* b_hh      = (const float*)d_in[9];
    const float* W_w       = (const float*)d_in[10];
    const float* W_b       = (const float*)d_in[11];
    const float* Wp_w      = (const float*)d_in[12];
    const float* Wp_b      = (const float*)d_in[13];
    const float* f_w       = (const float*)d_in[14];
    float* out = (float*)d_out;

    void* tmp;
    __nv_bfloat16 *Xbf_p, *Wih_p, *h_p, *Wbox_p, *Wq_p, *box_p;
    float *Xg_p, *qp_p, *Z_p;
    cudaGetSymbolAddress(&tmp, g_Xbf);  Xbf_p  = (__nv_bfloat16*)tmp;
    cudaGetSymbolAddress(&tmp, g_Wih);  Wih_p  = (__nv_bfloat16*)tmp;
    cudaGetSymbolAddress(&tmp, g_h);    h_p    = (__nv_bfloat16*)tmp;
    cudaGetSymbolAddress(&tmp, g_Wbox); Wbox_p = (__nv_bfloat16*)tmp;
    cudaGetSymbolAddress(&tmp, g_Wq);   Wq_p   = (__nv_bfloat16*)tmp;
    cudaGetSymbolAddress(&tmp, g_box);  box_p  = (__nv_bfloat16*)tmp;
    cudaGetSymbolAddress(&tmp, g_Xg);   Xg_p   = (float*)tmp;
    cudaGetSymbolAddress(&tmp, g_qp);   qp_p   = (float*)tmp;
    cudaGetSymbolAddress(&tmp, g_Z);    Z_p    = (float*)tmp;

    // -------- prep / conversion --------
    prep_x_kernel   <<<(T_ * B_ * E_PAD + 255) / 256, 256>>>(q_feats);
    prep_wih_kernel <<<(G4H * E_PAD + 255) / 256, 256>>>(W_ih);
    prep_whh_kernel <<<(G4H * QH) / 256, 256>>>(W_hh);
    prep_bias_kernel<<<G4H / 256, 256>>>(b_ih, b_hh);
    prep_wbox_kernel<<<(NBIG * ICNN) / 256, 256>>>(W_w, Wp_w);
    prep_wq_kernel  <<<(NBIG * QH) / 256, 256>>>(W_w, Wp_w);
    prep_small_kernel<<<((NBIG + HID_) + 255) / 256, 256>>>(W_b, Wp_b, f_w);
    conv_box_kernel <<<(ROWS_BIG * (size_t)ICNN) / 4 / 256, 256>>>(box_feats);

    // -------- LSTM input projections: Xg[3584,4096] = Xbf * Wih^T --------
    gemm_bf16_nt<<<dim3(G4H / 128, (T_ * B_) / 128), 256>>>(Xbf_p, Wih_p, Xg_p, E_PAD, G4H);

    // -------- fused persistent LSTM (14 steps, one launch) --------
    lstm_persistent_kernel<<<dim3(G4H / 128, B_ / 64), 256>>>();

    // -------- question projections: qp[256,1024] = h * Wq^T --------
    gemm_bf16_nt<<<dim3(NBIG / 128, B_ / 128), 256>>>(h_p, Wq_p, qp_p, QH, NBIG);

    // -------- big box GEMM: Z[25600,1024] = box * Wbox^T --------
    gemm_bf16_nt<<<dim3(NBIG / 128, ROWS_BIG / 128), 256>>>(box_p, Wbox_p, Z_p, ICNN, NBIG);

    // -------- scores + masked ragged sum --------
    score_kernel<<<ROWS_BIG, 128>>>();
    final_kernel<<<B_, 32>>>(index, out);
}

// round 5
// speedup vs baseline: 1.5586x; 1.2442x over previous
#include <cuda_runtime.h>
#include <cuda_bf16.h>
#include <cstdint>
#include <cstddef>

// ---------------- problem constants ----------------
#define B_      256
#define T_      14
#define E_RAW   300
#define E_PAD   320
#define QH      1024
#define G4H     4096
#define ICNN    2048
#define MAXN_   100
#define HID_    512
#define ROWS_BIG (B_*MAXN_)   // 25600
#define NBIG     1024          // interleaved 2*HID

// ---------------- device scratch ----------------
__device__ __align__(16) __nv_bfloat16 g_Xbf [(size_t)T_*B_*E_PAD];
__device__ __align__(16) __nv_bfloat16 g_Wih [(size_t)G4H*E_PAD];
__device__ __align__(16) __nv_bfloat16 g_Whh [(size_t)G4H*QH];
__device__ __align__(16) float         g_bias[G4H];
__device__ __align__(16) float         g_Xg  [(size_t)T_*B_*G4H];
__device__ __align__(16) __nv_bfloat16 g_h   [(size_t)B_*QH];
__device__ __align__(16) __nv_bfloat16 g_Wbox[(size_t)NBIG*ICNN];
__device__ __align__(16) __nv_bfloat16 g_Wq  [(size_t)NBIG*QH];
__device__ __align__(16) float         g_mb  [NBIG];
__device__ __align__(16) float         g_fw  [HID_];
__device__ __align__(16) float         g_qp  [(size_t)B_*NBIG];
__device__ __align__(16) __nv_bfloat16 g_boxc[(size_t)ROWS_BIG*ICNN];   // compacted bf16 rows
__device__ __align__(16) float         g_part[(size_t)ROWS_BIG*32];     // per-row score partials
__device__ int      g_rowsrc[ROWS_BIG];   // compact row -> source row (b*100+n)
__device__ int      g_rowb  [ROWS_BIG];   // compact row -> batch b
__device__ int      g_prefix[B_];
__device__ int      g_nrows;
__device__ int      g_nrowsPad;
__device__ unsigned g_bar;

// ---------------- helpers ----------------
__device__ __forceinline__ void mma16816(float acc[4], const uint32_t a[4], const uint32_t b[2]) {
    asm volatile(
        "mma.sync.aligned.m16n8k16.row.col.f32.bf16.bf16.f32 "
        "{%0,%1,%2,%3}, {%4,%5,%6,%7}, {%8,%9}, {%0,%1,%2,%3};\n"
        : "+f"(acc[0]), "+f"(acc[1]), "+f"(acc[2]), "+f"(acc[3])
        : "r"(a[0]), "r"(a[1]), "r"(a[2]), "r"(a[3]), "r"(b[0]), "r"(b[1]));
}
__device__ __forceinline__ void cp_async16(void* smem, const void* gmem) {
    uint32_t sa = (uint32_t)__cvta_generic_to_shared(smem);
    asm volatile("cp.async.cg.shared.global [%0], [%1], 16;\n" :: "r"(sa), "l"(gmem));
}
#define CP_COMMIT() asm volatile("cp.async.commit_group;\n" ::)
#define CP_WAIT0()  asm volatile("cp.async.wait_group 0;\n" ::)
#define CP_WAIT1()  asm volatile("cp.async.wait_group 1;\n" ::)

__device__ __forceinline__ float sigf(float x) { return 1.f / (1.f + __expf(-x)); }
__device__ __forceinline__ float ftanh(float x) {
    x = fminf(fmaxf(x, -15.f), 15.f);
    float e = __expf(2.f * x);
    return __fdividef(e - 1.f, e + 1.f);
}

// ============================================================================
// Generic GEMM: C = A[M,K]*B[N,K]^T (bf16->fp32), 128x128x32, 2-stage cp.async.
// ============================================================================
__global__ __launch_bounds__(256, 2) void gemm_bf16_nt(
    const __nv_bfloat16* __restrict__ A,
    const __nv_bfloat16* __restrict__ B,
    float* __restrict__ C,
    int K, int N)
{
    __shared__ __align__(16) __nv_bfloat16 sA[2][128][40];
    __shared__ __align__(16) __nv_bfloat16 sB[2][128][40];

    const int tid  = threadIdx.x;
    const int warp = tid >> 5;
    const int lane = tid & 31;
    const int wm   = warp >> 2;
    const int wn   = warp & 3;
    const int g    = lane >> 2;
    const int tt   = lane & 3;

    const size_t m0 = (size_t)blockIdx.y * 128;
    const size_t n0 = (size_t)blockIdx.x * 128;

    const int r0  = tid >> 2;
    const int ch0 = tid & 3;
    const int r1  = r0 + 64;

    const __nv_bfloat16* Ag0 = A + (m0 + r0) * (size_t)K + ch0 * 8;
    const __nv_bfloat16* Ag1 = A + (m0 + r1) * (size_t)K + ch0 * 8;
    const __nv_bfloat16* Bg0 = B + (n0 + r0) * (size_t)K + ch0 * 8;
    const __nv_bfloat16* Bg1 = B + (n0 + r1) * (size_t)K + ch0 * 8;

    float acc[4][4][4];
    #pragma unroll
    for (int mi = 0; mi < 4; mi++)
        #pragma unroll
        for (int ni = 0; ni < 4; ni++)
            #pragma unroll
            for (int e = 0; e < 4; e++) acc[mi][ni][e] = 0.f;

    const int nk = K / 32;
    cp_async16(&sA[0][r0][ch0 * 8], Ag0);
    cp_async16(&sA[0][r1][ch0 * 8], Ag1);
    cp_async16(&sB[0][r0][ch0 * 8], Bg0);
    cp_async16(&sB[0][r1][ch0 * 8], Bg1);
    CP_COMMIT();

    for (int k = 0; k < nk; k++) {
        CP_WAIT0();
        __syncthreads();
        if (k + 1 < nk) {
            const int s  = (k + 1) & 1;
            const int ko = (k + 1) * 32;
            cp_async16(&sA[s][r0][ch0 * 8], Ag0 + ko);
            cp_async16(&sA[s][r1][ch0 * 8], Ag1 + ko);
            cp_async16(&sB[s][r0][ch0 * 8], Bg0 + ko);
            cp_async16(&sB[s][r1][ch0 * 8], Bg1 + ko);
        }
        CP_COMMIT();

        const int st = k & 1;
        #pragma unroll
        for (int kk = 0; kk < 2; kk++) {
            const int kb = kk * 16 + tt * 2;
            uint32_t af[4][4];
            uint32_t bfr[4][2];
            #pragma unroll
            for (int mi = 0; mi < 4; mi++) {
                const int r = wm * 64 + mi * 16;
                af[mi][0] = *(const uint32_t*)&sA[st][r + g    ][kb];
                af[mi][1] = *(const uint32_t*)&sA[st][r + 8 + g][kb];
                af[mi][2] = *(const uint32_t*)&sA[st][r + g    ][kb + 8];
                af[mi][3] = *(const uint32_t*)&sA[st][r + 8 + g][kb + 8];
            }
            #pragma unroll
            for (int ni = 0; ni < 4; ni++) {
                const int cc = wn * 32 + ni * 8;
                bfr[ni][0] = *(const uint32_t*)&sB[st][cc + g][kb];
                bfr[ni][1] = *(const uint32_t*)&sB[st][cc + g][kb + 8];
            }
            #pragma unroll
            for (int mi = 0; mi < 4; mi++)
                #pragma unroll
                for (int ni = 0; ni < 4; ni++)
                    mma16816(acc[mi][ni], af[mi], bfr[ni]);
        }
    }

    #pragma unroll
    for (int mi = 0; mi < 4; mi++) {
        const size_t row = m0 + wm * 64 + mi * 16 + g;
        #pragma unroll
        for (int ni = 0; ni < 4; ni++) {
            const size_t col = n0 + wn * 32 + ni * 8 + tt * 2;
            *(float2*)&C[row       * (size_t)N + col] = make_float2(acc[mi][ni][0], acc[mi][ni][1]);
            *(float2*)&C[(row + 8) * (size_t)N + col] = make_float2(acc[mi][ni][2], acc[mi][ni][3]);
        }
    }
}

// ============================================================================
// Fused box GEMM + score partial epilogue. A = g_boxc (compacted), B = g_Wbox.
// K=2048, tile 128x128, 3-stage cp.async, dynamic smem, row early-exit.
// ============================================================================
__global__ __launch_bounds__(256, 2) void gemm_box_fused()
{
    extern __shared__ __align__(16) __nv_bfloat16 dyns[];
    typedef __nv_bfloat16 Tile[128][40];
    Tile* sA = (Tile*)dyns;                     // 3 stages
    Tile* sB = (Tile*)(dyns + 3 * 128 * 40);    // 3 stages

    const int m0 = blockIdx.y * 128;
    if (m0 >= g_nrowsPad) return;

    const int tid  = threadIdx.x;
    const int warp = tid >> 5;
    const int lane = tid & 31;
    const int wm   = warp >> 2;
    const int wn   = warp & 3;
    const int g    = lane >> 2;
    const int tt   = lane & 3;
    const int n0   = blockIdx.x * 128;

    const int r0  = tid >> 2;
    const int ch0 = tid & 3;
    const int r1  = r0 + 64;

    const __nv_bfloat16* Ag0 = g_boxc + (size_t)(m0 + r0) * ICNN + ch0 * 8;
    const __nv_bfloat16* Ag1 = g_boxc + (size_t)(m0 + r1) * ICNN + ch0 * 8;
    const __nv_bfloat16* Bg0 = g_Wbox + (size_t)(n0 + r0) * ICNN + ch0 * 8;
    const __nv_bfloat16* Bg1 = g_Wbox + (size_t)(n0 + r1) * ICNN + ch0 * 8;

    float acc[4][4][4];
    #pragma unroll
    for (int mi = 0; mi < 4; mi++)
        #pragma unroll
        for (int ni = 0; ni < 4; ni++)
            #pragma unroll
            for (int e = 0; e < 4; e++) acc[mi][ni][e] = 0.f;

    const int nk = ICNN / 32;   // 64

    #pragma unroll
    for (int p = 0; p < 2; p++) {
        const int ko = p * 32;
        cp_async16(&sA[p][r0][ch0 * 8], Ag0 + ko);
        cp_async16(&sA[p][r1][ch0 * 8], Ag1 + ko);
        cp_async16(&sB[p][r0][ch0 * 8], Bg0 + ko);
        cp_async16(&sB[p][r1][ch0 * 8], Bg1 + ko);
        CP_COMMIT();
    }

    int s2 = 2;
    for (int k = 0; k < nk; k++) {
        CP_WAIT1();
        __syncthreads();
        if (k + 2 < nk) {
            const int ko = (k + 2) * 32;
            cp_async16(&sA[s2][r0][ch0 * 8], Ag0 + ko);
            cp_async16(&sA[s2][r1][ch0 * 8], Ag1 + ko);
            cp_async16(&sB[s2][r0][ch0 * 8], Bg0 + ko);
            cp_async16(&sB[s2][r1][ch0 * 8], Bg1 + ko);
        }
        CP_COMMIT();

        const int st = (s2 + 1 >= 3) ? (s2 + 1 - 3) : (s2 + 1);   // == k%3
        #pragma unroll
        for (int kk = 0; kk < 2; kk++) {
            const int kb = kk * 16 + tt * 2;
            uint32_t af[4][4];
            uint32_t bfr[4][2];
            #pragma unroll
            for (int mi = 0; mi < 4; mi++) {
                const int r = wm * 64 + mi * 16;
                af[mi][0] = *(const uint32_t*)&sA[st][r + g    ][kb];
                af[mi][1] = *(const uint32_t*)&sA[st][r + 8 + g][kb];
                af[mi][2] = *(const uint32_t*)&sA[st][r + g    ][kb + 8];
                af[mi][3] = *(const uint32_t*)&sA[st][r + 8 + g][kb + 8];
            }
            #pragma unroll
            for (int ni = 0; ni < 4; ni++) {
                const int cc = wn * 32 + ni * 8;
                bfr[ni][0] = *(const uint32_t*)&sB[st][cc + g][kb];
                bfr[ni][1] = *(const uint32_t*)&sB[st][cc + g][kb + 8];
            }
            #pragma unroll
            for (int mi = 0; mi < 4; mi++)
                #pragma unroll
                for (int ni = 0; ni < 4; ni++)
                    mma16816(acc[mi][ni], af[mi], bfr[ni]);
        }
        s2 = (s2 + 1 >= 3) ? 0 : (s2 + 1);
    }

    // ---------------- fused score epilogue ----------------
    float fwv[4];
    float2 mbv[4];
    #pragma unroll
    for (int ni = 0; ni < 4; ni++) {
        const int col = n0 + wn * 32 + ni * 8 + tt * 2;   // even
        fwv[ni] = g_fw[col >> 1];
        mbv[ni] = *(const float2*)&g_mb[col];
    }

    #pragma unroll
    for (int mi = 0; mi < 4; mi++) {
        #pragma unroll
        for (int ro = 0; ro < 2; ro++) {
            const int row = m0 + wm * 64 + mi * 16 + g + ro * 8;
            const int b = g_rowb[row];
            const float* qpb = g_qp + (size_t)b * NBIG;
            float p = 0.f;
            #pragma unroll
            for (int ni = 0; ni < 4; ni++) {
                const float2 q = *(const float2*)&qpb[n0 + wn * 32 + ni * 8 + tt * 2];
                const float z1 = acc[mi][ni][ro * 2 + 0] + q.x + mbv[ni].x;
                const float z2 = acc[mi][ni][ro * 2 + 1] + q.y + mbv[ni].y;
                p += fwv[ni] * ftanh(z1) * sigf(z2);
            }
            p += __shfl_xor_sync(0xffffffffu, p, 1);
            p += __shfl_xor_sync(0xffffffffu, p, 2);
            if (tt == 0) g_part[(size_t)row * 32 + blockIdx.x * 4 + wn] = p;
        }
    }
}

// ============================================================================
// Persistent fused LSTM: 14 steps, grid barrier, c in regs.
// ============================================================================
__global__ __launch_bounds__(256) void lstm_persistent_kernel()
{
    __shared__ __align__(16) __nv_bfloat16 sA[2][64][40];
    __shared__ __align__(16) __nv_bfloat16 sB[2][128][40];

    const int tid  = threadIdx.x;
    const int warp = tid >> 5;
    const int lane = tid & 31;
    const int wm   = warp >> 2;
    const int wn   = warp & 3;
    const int g    = lane >> 2;
    const int tt   = lane & 3;

    const int m0 = blockIdx.y * 64;
    const int n0 = blockIdx.x * 128;

    const int rA  = tid >> 2;
    const int ch0 = tid & 3;
    const int rB1 = rA + 64;

    const __nv_bfloat16* Ag  = g_h   + (size_t)(m0 + rA)  * QH + ch0 * 8;
    const __nv_bfloat16* Bg0 = g_Whh + (size_t)(n0 + rA)  * QH + ch0 * 8;
    const __nv_bfloat16* Bg1 = g_Whh + (size_t)(n0 + rB1) * QH + ch0 * 8;

    float bias0[4], bias1[4];
    #pragma unroll
    for (int ni = 0; ni < 4; ni++) {
        const int c = n0 + wn * 32 + ni * 8 + 2 * tt;
        bias0[ni] = g_bias[c];
        bias1[ni] = g_bias[c + 1];
    }

    float creg[2][4][2];
    #pragma unroll
    for (int mi = 0; mi < 2; mi++)
        #pragma unroll
        for (int ni = 0; ni < 4; ni++) { creg[mi][ni][0] = 0.f; creg[mi][ni][1] = 0.f; }

    for (int t = 0; t < T_; t++) {
        float acc[2][4][4];
        #pragma unroll
        for (int mi = 0; mi < 2; mi++)
            #pragma unroll
            for (int ni = 0; ni < 4; ni++)
                #pragma unroll
                for (int e = 0; e < 4; e++) acc[mi][ni][e] = 0.f;

        if (t > 0) {
            cp_async16(&sA[0][rA][ch0 * 8], Ag);
            cp_async16(&sB[0][rA][ch0 * 8], Bg0);
            cp_async16(&sB[0][rB1][ch0 * 8], Bg1);
            CP_COMMIT();
            for (int k = 0; k < 32; k++) {
                CP_WAIT0();
                __syncthreads();
                if (k < 31) {
                    const int s  = (k + 1) & 1;
                    const int ko = (k + 1) * 32;
                    cp_async16(&sA[s][rA][ch0 * 8], Ag + ko);
                    cp_async16(&sB[s][rA][ch0 * 8], Bg0 + ko);
                    cp_async16(&sB[s][rB1][ch0 * 8], Bg1 + ko);
                }
                CP_COMMIT();

                const int st = k & 1;
                #pragma unroll
                for (int kk = 0; kk < 2; kk++) {
                    const int kb = kk * 16 + tt * 2;
                    uint32_t af[2][4];
                    uint32_t bfr[4][2];
                    #pragma unroll
                    for (int mi = 0; mi < 2; mi++) {
                        const int r = wm * 32 + mi * 16;
                        af[mi][0] = *(const uint32_t*)&sA[st][r + g    ][kb];
                        af[mi][1] = *(const uint32_t*)&sA[st][r + 8 + g][kb];
                        af[mi][2] = *(const uint32_t*)&sA[st][r + g    ][kb + 8];
                        af[mi][3] = *(const uint32_t*)&sA[st][r + 8 + g][kb + 8];
                    }
                    #pragma unroll
                    for (int ni = 0; ni < 4; ni++) {
                        const int cc = wn * 32 + ni * 8;
                        bfr[ni][0] = *(const uint32_t*)&sB[st][cc + g][kb];
                        bfr[ni][1] = *(const uint32_t*)&sB[st][cc + g][kb + 8];
                    }
                    #pragma unroll
                    for (int mi = 0; mi < 2; mi++)
                        #pragma unroll
                        for (int ni = 0; ni < 4; ni++)
                            mma16816(acc[mi][ni], af[mi], bfr[ni]);
                }
            }
        }

        const float* xg = g_Xg + (size_t)(t * B_ + m0) * G4H;
        #pragma unroll
        for (int mi = 0; mi < 2; mi++) {
            #pragma unroll
            for (int ro = 0; ro < 2; ro++) {
                const int rowl = wm * 32 + mi * 16 + g + ro * 8;
                #pragma unroll
                for (int ni = 0; ni < 4; ni++) {
                    const int cl = wn * 32 + ni * 8 + 2 * tt;
                    const float2 x = *(const float2*)(xg + (size_t)rowl * G4H + n0 + cl);
                    const float v0 = acc[mi][ni][ro * 2 + 0] + x.x + bias0[ni];
                    const float v1 = acc[mi][ni][ro * 2 + 1] + x.y + bias1[ni];
                    const float p0 = __shfl_xor_sync(0xffffffffu, v0, 1);
                    const float p1 = __shfl_xor_sync(0xffffffffu, v1, 1);
                    if ((tt & 1) == 0) {
                        const float ii = sigf(v0);
                        const float ff = sigf(v1);
                        const float gg = tanhf(p0);
                        const float oo = sigf(p1);
                        const float cn = ff * creg[mi][ni][ro] + ii * gg;
                        creg[mi][ni][ro] = cn;
                        const int kg = (n0 + cl) >> 2;
                        g_h[(size_t)(m0 + rowl) * QH + kg] = __float2bfloat16(oo * tanhf(cn));
                    }
                }
            }
        }

        if (t < T_ - 1) {
            __threadfence();
            __syncthreads();
            if (tid == 0) {
                atomicAdd(&g_bar, 1u);
                const unsigned target = 128u * (unsigned)(t + 1);
                while (atomicAdd(&g_bar, 0u) < target) { __nanosleep(64); }
            }
            __syncthreads();
        }
    }
}

// ---------------- prep kernels ----------------
__device__ __forceinline__ int lstm_src_row(int j) { return (j & 3) * QH + (j >> 2); }

__global__ void prep_x_kernel(const float* __restrict__ q_feats) {
    int idx = blockIdx.x * blockDim.x + threadIdx.x;
    if (idx >= T_ * B_ * E_PAD) return;
    int r = idx / E_PAD, e = idx % E_PAD;
    int t = r >> 8, b = r & 255;
    float v = (e < E_RAW) ? q_feats[((size_t)b * T_ + t) * E_RAW + e] : 0.f;
    g_Xbf[idx] = __float2bfloat16(v);
}

__global__ void prep_wih_kernel(const float* __restrict__ W_ih) {
    int idx = blockIdx.x * blockDim.x + threadIdx.x;
    if (idx >= G4H * E_PAD) return;
    int j = idx / E_PAD, e = idx % E_PAD;
    int src = lstm_src_row(j);
    float v = (e < E_RAW) ? W_ih[(size_t)src * E_RAW + e] : 0.f;
    g_Wih[idx] = __float2bfloat16(v);
}

__global__ void prep_whh_kernel(const float* __restrict__ W_hh) {
    int idx = blockIdx.x * blockDim.x + threadIdx.x;
    if (idx >= G4H * QH) return;
    int j = idx >> 10, e = idx & 1023;
    int src = lstm_src_row(j);
    g_Whh[idx] = __float2bfloat16(W_hh[(size_t)src * QH + e]);
}

__global__ void prep_bias_kernel(const float* __restrict__ b_ih, const float* __restrict__ b_hh) {
    int j = blockIdx.x * blockDim.x + threadIdx.x;
    if (j == 0) g_bar = 0u;
    if (j >= G4H) return;
    int src = lstm_src_row(j);
    g_bias[j] = b_ih[src] + b_hh[src];
}

// single-block scan: build compacted row list from index[]
__global__ void rowmap_kernel(const int* __restrict__ index) {
    __shared__ int sc[B_];
    const int b = threadIdx.x;   // 256 threads
    int cnt = index[b];
    cnt = max(0, min(cnt, MAXN_));
    sc[b] = cnt;
    __syncthreads();
    for (int off = 1; off < B_; off <<= 1) {
        int v = (b >= off) ? sc[b - off] : 0;
        __syncthreads();
        sc[b] += v;
        __syncthreads();
    }
    const int pref = sc[b] - cnt;
    g_prefix[b] = pref;
    for (int j = 0; j < cnt; j++) {
        g_rowsrc[pref + j] = b * MAXN_ + j;
        g_rowb[pref + j]   = b;
    }
    const int total = sc[B_ - 1];
    const int pad = (total + 127) & ~127;
    if (b == 0) { g_nrows = total; g_nrowsPad = pad; }
    for (int j = total + b; j < pad; j += B_) g_rowb[j] = 0;
}

__global__ void prep_wbox_kernel(const float* __restrict__ W_w, const float* __restrict__ Wp_w) {
    int idx = blockIdx.x * blockDim.x + threadIdx.x;
    if (idx >= NBIG * ICNN) return;
    int j = idx >> 11, cc = idx & 2047;
    int h = j >> 1;
    const float* s = (j & 1) ? Wp_w : W_w;
    g_Wbox[idx] = __float2bfloat16(s[(size_t)h * (ICNN + QH) + cc]);
}

__global__ void prep_wq_kernel(const float* __restrict__ W_w, const float* __restrict__ Wp_w) {
    int idx = blockIdx.x * blockDim.x + threadIdx.x;
    if (idx >= NBIG * QH) return;
    int j = idx >> 10, cc = idx & 1023;
    int h = j >> 1;
    const float* s = (j & 1) ? Wp_w : W_w;
    g_Wq[idx] = __float2bfloat16(s[(size_t)h * (ICNN + QH) + ICNN + cc]);
}

__global__ void prep_small_kernel(const float* __restrict__ W_b, const float* __restrict__ Wp_b,
                                  const float* __restrict__ f_w) {
    int idx = blockIdx.x * blockDim.x + threadIdx.x;
    if (idx < NBIG) {
        g_mb[idx] = (idx & 1) ? Wp_b[idx >> 1] : W_b[idx >> 1];
    } else if (idx < NBIG + HID_) {
        g_fw[idx - NBIG] = f_w[idx - NBIG];
    }
}

// gather + convert only valid box rows (zero padded tail rows)
__global__ void conv_boxc_kernel(const float* __restrict__ box) {
    const int cr = blockIdx.x;                // one 2048-wide row per block
    if (cr >= g_nrowsPad) return;
    uint4* dst = (uint4*)(g_boxc + (size_t)cr * ICNN) + threadIdx.x;  // 8 bf16 per uint4
    if (cr < g_nrows) {
        const float4* src = (const float4*)(box + (size_t)g_rowsrc[cr] * ICNN) + threadIdx.x * 2;
        float4 a = src[0];
        float4 c = src[1];
        uint4 o;
        __nv_bfloat162 p;
        p = __floats2bfloat162_rn(a.x, a.y); o.x = *(uint32_t*)&p;
        p = __floats2bfloat162_rn(a.z, a.w); o.y = *(uint32_t*)&p;
        p = __floats2bfloat162_rn(c.x, c.y); o.z = *(uint32_t*)&p;
        p = __floats2bfloat162_rn(c.z, c.w); o.w = *(uint32_t*)&p;
        dst[0] = o;
    } else {
        dst[0] = make_uint4(0u, 0u, 0u, 0u);
    }
}

// ---------------- final: per-row sum of 32 partials + sigmoid + ragged sum ----------------
__global__ void final_kernel(const int* __restrict__ index, float* __restrict__ out) {
    const int b = blockIdx.x;
    const int lane = threadIdx.x;
    int cnt = index[b];
    cnt = max(0, min(cnt, MAXN_));
    const int pref = g_prefix[b];
    float s = 0.f;
    for (int r = lane; r < cnt; r += 32) {
        const float4* pp = (const float4*)&g_part[(size_t)(pref + r) * 32];
        float t = 0.f;
        #pragma unroll
        for (int j = 0; j < 8; j++) {
            float4 v = pp[j];
            t += (v.x + v.y) + (v.z + v.w);
        }
        s += sigf(t);
    }
    #pragma unroll
    for (int off = 16; off > 0; off >>= 1) s += __shfl_down_sync(0xffffffffu, s, off);
    if (lane == 0) out[b] = s;
}

// ---------------- launch ----------------
extern "C" void kernel_launch(void* const* d_in, const int* in_sizes, int n_in,
                              void* d_out, int out_size) {
    (void)in_sizes; (void)n_in; (void)out_size;
    const float* box_feats = (const float*)d_in[2];
    const float* q_feats   = (const float*)d_in[3];
    const int*   index     = (const int*)  d_in[5];
    const float* W_ih      = (const float*)d_in[6];
    const float* W_hh      = (const float*)d_in[7];
    const float* b_ih      = (const float*)d_in[8];
    const float* b_hh      = (const float*)d_in[9];
    const float* W_w       = (const float*)d_in[10];
    const float* W_b       = (const float*)d_in[11];
    const float* Wp_w      = (const float*)d_in[12];
    const float* Wp_b      = (const float*)d_in[13];
    const float* f_w       = (const float*)d_in[14];
    float* out = (float*)d_out;

    void* tmp;
    __nv_bfloat16 *Xbf_p, *Wih_p, *h_p, *Wq_p;
    float *Xg_p, *qp_p;
    cudaGetSymbolAddress(&tmp, g_Xbf); Xbf_p = (__nv_bfloat16*)tmp;
    cudaGetSymbolAddress(&tmp, g_Wih); Wih_p = (__nv_bfloat16*)tmp;
    cudaGetSymbolAddress(&tmp, g_h);   h_p   = (__nv_bfloat16*)tmp;
    cudaGetSymbolAddress(&tmp, g_Wq);  Wq_p  = (__nv_bfloat16*)tmp;
    cudaGetSymbolAddress(&tmp, g_Xg);  Xg_p  = (float*)tmp;
    cudaGetSymbolAddress(&tmp, g_qp);  qp_p  = (float*)tmp;

    // no static guard: set attribute unconditionally (host-side, idempotent,
    // not a stream op -> graph-capture safe)
    const int box_smem = 3 * 2 * 128 * 40 * (int)sizeof(__nv_bfloat16);   // 61440
    cudaFuncSetAttribute(gemm_box_fused, cudaFuncAttributeMaxDynamicSharedMemorySize, box_smem);

    // idx0..2: LSTM input prep
    prep_x_kernel   <<<(T_ * B_ * E_PAD + 255) / 256, 256>>>(q_feats);
    prep_wih_kernel <<<(G4H * E_PAD + 255) / 256, 256>>>(W_ih);
    prep_whh_kernel <<<(G4H * QH) / 256, 256>>>(W_hh);
    // idx3: Xg GEMM (so the profiler's fixed capture slot lands on a real GEMM)
    gemm_bf16_nt<<<dim3(G4H / 128, (T_ * B_) / 128), 256>>>(Xbf_p, Wih_p, Xg_p, E_PAD, G4H);
    // idx4+: remaining prep
    prep_bias_kernel<<<G4H / 256, 256>>>(b_ih, b_hh);
    rowmap_kernel   <<<1, B_>>>(index);
    prep_small_kernel<<<((NBIG + HID_) + 255) / 256, 256>>>(W_b, Wp_b, f_w);
    prep_wbox_kernel<<<(NBIG * ICNN) / 256, 256>>>(W_w, Wp_w);
    prep_wq_kernel  <<<(NBIG * QH) / 256, 256>>>(W_w, Wp_w);
    conv_boxc_kernel<<<ROWS_BIG, 256>>>(box_feats);

    // LSTM chain
    lstm_persistent_kernel<<<dim3(G4H / 128, B_ / 64), 256>>>();
    gemm_bf16_nt<<<dim3(NBIG / 128, B_ / 128), 256>>>(h_p, Wq_p, qp_p, QH, NBIG);

    // fused box GEMM + score partials (compacted rows)
    gemm_box_fused<<<dim3(NBIG / 128, ROWS_BIG / 128), 256, box_smem>>>();

    // ragged reduction
    final_kernel<<<B_, 32>>>(index, out);
}

// round 6
// speedup vs baseline: 1.7530x; 1.1247x over previous
#include <cuda_runtime.h>
#include <cuda_bf16.h>
#include <cstdint>
#include <cstddef>

// ---------------- problem constants ----------------
#define B_      256
#define T_      14
#define E_RAW   300
#define E_PAD   320
#define QH      1024
#define G4H     4096
#define ICNN    2048
#define MAXN_   100
#define HID_    512
#define ROWS_BIG (B_*MAXN_)   // 25600
#define NBIG     1024          // interleaved 2*HID

// ---------------- device scratch ----------------
__device__ __align__(16) __nv_bfloat16 g_Xbf [(size_t)T_*B_*E_PAD];
__device__ __align__(16) __nv_bfloat16 g_Wih [(size_t)G4H*E_PAD];
__device__ __align__(16) __nv_bfloat16 g_Whh [(size_t)G4H*QH];
__device__ __align__(16) float         g_bias[G4H];
__device__ __align__(16) float         g_Xg  [(size_t)T_*B_*G4H];
__device__ __align__(16) __nv_bfloat16 g_h   [(size_t)B_*QH];
__device__ __align__(16) __nv_bfloat16 g_Wbox[(size_t)NBIG*ICNN];
__device__ __align__(16) __nv_bfloat16 g_Wq  [(size_t)NBIG*QH];
__device__ __align__(16) float         g_mb  [NBIG];
__device__ __align__(16) float         g_fw  [HID_];
__device__ __align__(16) float         g_qp  [(size_t)B_*NBIG];
__device__ __align__(16) __nv_bfloat16 g_boxc[(size_t)ROWS_BIG*ICNN];   // compacted bf16 rows
__device__ __align__(16) float         g_part[(size_t)ROWS_BIG*32];     // per-row score partials
__device__ int      g_rowsrc[ROWS_BIG];
__device__ int      g_rowb  [ROWS_BIG];
__device__ int      g_prefix[B_];
__device__ int      g_nrows;
__device__ int      g_nrowsPad;
__device__ unsigned g_bar;

// ---------------- helpers ----------------
__device__ __forceinline__ void mma16816(float acc[4], const uint32_t a[4], const uint32_t b[2]) {
    asm volatile(
        "mma.sync.aligned.m16n8k16.row.col.f32.bf16.bf16.f32 "
        "{%0,%1,%2,%3}, {%4,%5,%6,%7}, {%8,%9}, {%0,%1,%2,%3};\n"
        : "+f"(acc[0]), "+f"(acc[1]), "+f"(acc[2]), "+f"(acc[3])
        : "r"(a[0]), "r"(a[1]), "r"(a[2]), "r"(a[3]), "r"(b[0]), "r"(b[1]));
}
__device__ __forceinline__ void cp_async16(void* smem, const void* gmem) {
    uint32_t sa = (uint32_t)__cvta_generic_to_shared(smem);
    asm volatile("cp.async.cg.shared.global [%0], [%1], 16;\n" :: "r"(sa), "l"(gmem));
}
#define CP_COMMIT() asm volatile("cp.async.commit_group;\n" ::)
#define CP_WAIT0()  asm volatile("cp.async.wait_group 0;\n" ::)
#define CP_WAIT1()  asm volatile("cp.async.wait_group 1;\n" ::)

// ldmatrix x4: loads four 8x8 b16 tiles; each lane supplies one row address.
__device__ __forceinline__ void ldsm_x4(uint32_t* r, const __nv_bfloat16* p) {
    uint32_t a = (uint32_t)__cvta_generic_to_shared(p);
    asm volatile("ldmatrix.sync.aligned.m8n8.x4.shared.b16 {%0,%1,%2,%3}, [%4];"
                 : "=r"(r[0]), "=r"(r[1]), "=r"(r[2]), "=r"(r[3]) : "r"(a));
}

__device__ __forceinline__ float sigf(float x) { return 1.f / (1.f + __expf(-x)); }
__device__ __forceinline__ float ftanh(float x) {
    x = fminf(fmaxf(x, -15.f), 15.f);
    float e = __expf(2.f * x);
    return __fdividef(e - 1.f, e + 1.f);
}

// ============================================================================
// Generic GEMM: C = A[M,K]*B[N,K]^T (bf16->fp32), 128x128x32, 3-stage cp.async,
// dynamic smem, ldmatrix fragment loads. M%128==0, N%128==0, K%32==0, K/32>=2.
// ============================================================================
__global__ __launch_bounds__(256, 2) void gemm_bf16_nt(
    const __nv_bfloat16* __restrict__ A,
    const __nv_bfloat16* __restrict__ B,
    float* __restrict__ C,
    int K, int N)
{
    extern __shared__ __align__(16) __nv_bfloat16 dyns[];
    typedef __nv_bfloat16 Tile[128][40];
    Tile* sA = (Tile*)dyns;
    Tile* sB = (Tile*)(dyns + 3 * 128 * 40);

    const int tid  = threadIdx.x;
    const int warp = tid >> 5;
    const int lane = tid & 31;
    const int wm   = warp >> 2;
    const int wn   = warp & 3;
    const int g    = lane >> 2;
    const int tt   = lane & 3;

    // ldmatrix per-lane addressing
    const int arow = lane & 15;
    const int acol = (lane >> 4) * 8;
    const int brow = ((lane >> 4) & 1) * 8 + (lane & 7);
    const int bcol = ((lane >> 3) & 1) * 8;

    const size_t m0 = (size_t)blockIdx.y * 128;
    const size_t n0 = (size_t)blockIdx.x * 128;

    const int r0  = tid >> 2;
    const int ch0 = tid & 3;
    const int r1  = r0 + 64;

    const __nv_bfloat16* Ag0 = A + (m0 + r0) * (size_t)K + ch0 * 8;
    const __nv_bfloat16* Ag1 = A + (m0 + r1) * (size_t)K + ch0 * 8;
    const __nv_bfloat16* Bg0 = B + (n0 + r0) * (size_t)K + ch0 * 8;
    const __nv_bfloat16* Bg1 = B + (n0 + r1) * (size_t)K + ch0 * 8;

    float acc[4][4][4];
    #pragma unroll
    for (int mi = 0; mi < 4; mi++)
        #pragma unroll
        for (int ni = 0; ni < 4; ni++)
            #pragma unroll
            for (int e = 0; e < 4; e++) acc[mi][ni][e] = 0.f;

    const int nk = K / 32;
    #pragma unroll
    for (int p = 0; p < 2; p++) {
        const int ko = p * 32;
        cp_async16(&sA[p][r0][ch0 * 8], Ag0 + ko);
        cp_async16(&sA[p][r1][ch0 * 8], Ag1 + ko);
        cp_async16(&sB[p][r0][ch0 * 8], Bg0 + ko);
        cp_async16(&sB[p][r1][ch0 * 8], Bg1 + ko);
        CP_COMMIT();
    }

    int s2 = 2;
    for (int k = 0; k < nk; k++) {
        CP_WAIT1();
        __syncthreads();
        if (k + 2 < nk) {
            const int ko = (k + 2) * 32;
            cp_async16(&sA[s2][r0][ch0 * 8], Ag0 + ko);
            cp_async16(&sA[s2][r1][ch0 * 8], Ag1 + ko);
            cp_async16(&sB[s2][r0][ch0 * 8], Bg0 + ko);
            cp_async16(&sB[s2][r1][ch0 * 8], Bg1 + ko);
        }
        CP_COMMIT();

        const int st = (s2 + 1 >= 3) ? (s2 + 1 - 3) : (s2 + 1);   // == k%3
        #pragma unroll
        for (int kk = 0; kk < 2; kk++) {
            const int kb = kk * 16;
            uint32_t af[4][4];
            #pragma unroll
            for (int mi = 0; mi < 4; mi++)
                ldsm_x4(af[mi], &sA[st][wm * 64 + mi * 16 + arow][kb + acol]);
            uint32_t bfr[4][2];
            #pragma unroll
            for (int nj = 0; nj < 2; nj++) {
                uint32_t bt[4];
                ldsm_x4(bt, &sB[st][wn * 32 + nj * 16 + brow][kb + bcol]);
                bfr[2*nj][0] = bt[0]; bfr[2*nj][1] = bt[1];
                bfr[2*nj+1][0] = bt[2]; bfr[2*nj+1][1] = bt[3];
            }
            #pragma unroll
            for (int mi = 0; mi < 4; mi++)
                #pragma unroll
                for (int ni = 0; ni < 4; ni++)
                    mma16816(acc[mi][ni], af[mi], bfr[ni]);
        }
        s2 = (s2 + 1 >= 3) ? 0 : (s2 + 1);
    }

    #pragma unroll
    for (int mi = 0; mi < 4; mi++) {
        const size_t row = m0 + wm * 64 + mi * 16 + g;
        #pragma unroll
        for (int ni = 0; ni < 4; ni++) {
            const size_t col = n0 + wn * 32 + ni * 8 + tt * 2;
            *(float2*)&C[row       * (size_t)N + col] = make_float2(acc[mi][ni][0], acc[mi][ni][1]);
            *(float2*)&C[(row + 8) * (size_t)N + col] = make_float2(acc[mi][ni][2], acc[mi][ni][3]);
        }
    }
}

// ============================================================================
// Fused box GEMM + score partial epilogue (compacted rows), 3-stage, ldmatrix.
// ============================================================================
__global__ __launch_bounds__(256, 2) void gemm_box_fused()
{
    extern __shared__ __align__(16) __nv_bfloat16 dyns[];
    typedef __nv_bfloat16 Tile[128][40];
    Tile* sA = (Tile*)dyns;
    Tile* sB = (Tile*)(dyns + 3 * 128 * 40);

    const int m0 = blockIdx.y * 128;
    if (m0 >= g_nrowsPad) return;

    const int tid  = threadIdx.x;
    const int warp = tid >> 5;
    const int lane = tid & 31;
    const int wm   = warp >> 2;
    const int wn   = warp & 3;
    const int g    = lane >> 2;
    const int tt   = lane & 3;
    const int n0   = blockIdx.x * 128;

    const int arow = lane & 15;
    const int acol = (lane >> 4) * 8;
    const int brow = ((lane >> 4) & 1) * 8 + (lane & 7);
    const int bcol = ((lane >> 3) & 1) * 8;

    const int r0  = tid >> 2;
    const int ch0 = tid & 3;
    const int r1  = r0 + 64;

    const __nv_bfloat16* Ag0 = g_boxc + (size_t)(m0 + r0) * ICNN + ch0 * 8;
    const __nv_bfloat16* Ag1 = g_boxc + (size_t)(m0 + r1) * ICNN + ch0 * 8;
    const __nv_bfloat16* Bg0 = g_Wbox + (size_t)(n0 + r0) * ICNN + ch0 * 8;
    const __nv_bfloat16* Bg1 = g_Wbox + (size_t)(n0 + r1) * ICNN + ch0 * 8;

    float acc[4][4][4];
    #pragma unroll
    for (int mi = 0; mi < 4; mi++)
        #pragma unroll
        for (int ni = 0; ni < 4; ni++)
            #pragma unroll
            for (int e = 0; e < 4; e++) acc[mi][ni][e] = 0.f;

    const int nk = ICNN / 32;   // 64

    #pragma unroll
    for (int p = 0; p < 2; p++) {
        const int ko = p * 32;
        cp_async16(&sA[p][r0][ch0 * 8], Ag0 + ko);
        cp_async16(&sA[p][r1][ch0 * 8], Ag1 + ko);
        cp_async16(&sB[p][r0][ch0 * 8], Bg0 + ko);
        cp_async16(&sB[p][r1][ch0 * 8], Bg1 + ko);
        CP_COMMIT();
    }

    int s2 = 2;
    for (int k = 0; k < nk; k++) {
        CP_WAIT1();
        __syncthreads();
        if (k + 2 < nk) {
            const int ko = (k + 2) * 32;
            cp_async16(&sA[s2][r0][ch0 * 8], Ag0 + ko);
            cp_async16(&sA[s2][r1][ch0 * 8], Ag1 + ko);
            cp_async16(&sB[s2][r0][ch0 * 8], Bg0 + ko);
            cp_async16(&sB[s2][r1][ch0 * 8], Bg1 + ko);
        }
        CP_COMMIT();

        const int st = (s2 + 1 >= 3) ? (s2 + 1 - 3) : (s2 + 1);
        #pragma unroll
        for (int kk = 0; kk < 2; kk++) {
            const int kb = kk * 16;
            uint32_t af[4][4];
            #pragma unroll
            for (int mi = 0; mi < 4; mi++)
                ldsm_x4(af[mi], &sA[st][wm * 64 + mi * 16 + arow][kb + acol]);
            uint32_t bfr[4][2];
            #pragma unroll
            for (int nj = 0; nj < 2; nj++) {
                uint32_t bt[4];
                ldsm_x4(bt, &sB[st][wn * 32 + nj * 16 + brow][kb + bcol]);
                bfr[2*nj][0] = bt[0]; bfr[2*nj][1] = bt[1];
                bfr[2*nj+1][0] = bt[2]; bfr[2*nj+1][1] = bt[3];
            }
            #pragma unroll
            for (int mi = 0; mi < 4; mi++)
                #pragma unroll
                for (int ni = 0; ni < 4; ni++)
                    mma16816(acc[mi][ni], af[mi], bfr[ni]);
        }
        s2 = (s2 + 1 >= 3) ? 0 : (s2 + 1);
    }

    // ---------------- fused score epilogue ----------------
    float fwv[4];
    float2 mbv[4];
    #pragma unroll
    for (int ni = 0; ni < 4; ni++) {
        const int col = n0 + wn * 32 + ni * 8 + tt * 2;   // even
        fwv[ni] = g_fw[col >> 1];
        mbv[ni] = *(const float2*)&g_mb[col];
    }

    #pragma unroll
    for (int mi = 0; mi < 4; mi++) {
        #pragma unroll
        for (int ro = 0; ro < 2; ro++) {
            const int row = m0 + wm * 64 + mi * 16 + g + ro * 8;
            const int b = g_rowb[row];
            const float* qpb = g_qp + (size_t)b * NBIG;
            float p = 0.f;
            #pragma unroll
            for (int ni = 0; ni < 4; ni++) {
                const float2 q = *(const float2*)&qpb[n0 + wn * 32 + ni * 8 + tt * 2];
                const float z1 = acc[mi][ni][ro * 2 + 0] + q.x + mbv[ni].x;
                const float z2 = acc[mi][ni][ro * 2 + 1] + q.y + mbv[ni].y;
                p += fwv[ni] * ftanh(z1) * sigf(z2);
            }
            p += __shfl_xor_sync(0xffffffffu, p, 1);
            p += __shfl_xor_sync(0xffffffffu, p, 2);
            if (tt == 0) g_part[(size_t)row * 32 + blockIdx.x * 4 + wn] = p;
        }
    }
}

// ============================================================================
// Persistent fused LSTM: 14 steps, grid barrier, c in regs, 3-stage + ldmatrix.
// ============================================================================
__global__ __launch_bounds__(256) void lstm_persistent_kernel()
{
    __shared__ __align__(16) __nv_bfloat16 sA[3][64][40];
    __shared__ __align__(16) __nv_bfloat16 sB[3][128][40];

    const int tid  = threadIdx.x;
    const int warp = tid >> 5;
    const int lane = tid & 31;
    const int wm   = warp >> 2;
    const int wn   = warp & 3;
    const int g    = lane >> 2;
    const int tt   = lane & 3;

    const int arow = lane & 15;
    const int acol = (lane >> 4) * 8;
    const int brow = ((lane >> 4) & 1) * 8 + (lane & 7);
    const int bcol = ((lane >> 3) & 1) * 8;

    const int m0 = blockIdx.y * 64;
    const int n0 = blockIdx.x * 128;

    const int rA  = tid >> 2;
    const int ch0 = tid & 3;
    const int rB1 = rA + 64;

    const __nv_bfloat16* Ag  = g_h   + (size_t)(m0 + rA)  * QH + ch0 * 8;
    const __nv_bfloat16* Bg0 = g_Whh + (size_t)(n0 + rA)  * QH + ch0 * 8;
    const __nv_bfloat16* Bg1 = g_Whh + (size_t)(n0 + rB1) * QH + ch0 * 8;

    float bias0[4], bias1[4];
    #pragma unroll
    for (int ni = 0; ni < 4; ni++) {
        const int c = n0 + wn * 32 + ni * 8 + 2 * tt;
        bias0[ni] = g_bias[c];
        bias1[ni] = g_bias[c + 1];
    }

    float creg[2][4][2];
    #pragma unroll
    for (int mi = 0; mi < 2; mi++)
        #pragma unroll
        for (int ni = 0; ni < 4; ni++) { creg[mi][ni][0] = 0.f; creg[mi][ni][1] = 0.f; }

    for (int t = 0; t < T_; t++) {
        float acc[2][4][4];
        #pragma unroll
        for (int mi = 0; mi < 2; mi++)
            #pragma unroll
            for (int ni = 0; ni < 4; ni++)
                #pragma unroll
                for (int e = 0; e < 4; e++) acc[mi][ni][e] = 0.f;

        if (t > 0) {
            #pragma unroll
            for (int p = 0; p < 2; p++) {
                const int ko = p * 32;
                cp_async16(&sA[p][rA][ch0 * 8], Ag + ko);
                cp_async16(&sB[p][rA][ch0 * 8], Bg0 + ko);
                cp_async16(&sB[p][rB1][ch0 * 8], Bg1 + ko);
                CP_COMMIT();
            }
            int s2 = 2;
            for (int k = 0; k < 32; k++) {
                CP_WAIT1();
                __syncthreads();
                if (k + 2 < 32) {
                    const int ko = (k + 2) * 32;
                    cp_async16(&sA[s2][rA][ch0 * 8], Ag + ko);
                    cp_async16(&sB[s2][rA][ch0 * 8], Bg0 + ko);
                    cp_async16(&sB[s2][rB1][ch0 * 8], Bg1 + ko);
                }
                CP_COMMIT();

                const int st = (s2 + 1 >= 3) ? (s2 + 1 - 3) : (s2 + 1);
                #pragma unroll
                for (int kk = 0; kk < 2; kk++) {
                    const int kb = kk * 16;
                    uint32_t af[2][4];
                    #pragma unroll
                    for (int mi = 0; mi < 2; mi++)
                        ldsm_x4(af[mi], &sA[st][wm * 32 + mi * 16 + arow][kb + acol]);
                    uint32_t bfr[4][2];
                    #pragma unroll
                    for (int nj = 0; nj < 2; nj++) {
                        uint32_t bt[4];
                        ldsm_x4(bt, &sB[st][wn * 32 + nj * 16 + brow][kb + bcol]);
                        bfr[2*nj][0] = bt[0]; bfr[2*nj][1] = bt[1];
                        bfr[2*nj+1][0] = bt[2]; bfr[2*nj+1][1] = bt[3];
                    }
                    #pragma unroll
                    for (int mi = 0; mi < 2; mi++)
                        #pragma unroll
                        for (int ni = 0; ni < 4; ni++)
                            mma16816(acc[mi][ni], af[mi], bfr[ni]);
                }
                s2 = (s2 + 1 >= 3) ? 0 : (s2 + 1);
            }
        }

        const float* xg = g_Xg + (size_t)(t * B_ + m0) * G4H;
        #pragma unroll
        for (int mi = 0; mi < 2; mi++) {
            #pragma unroll
            for (int ro = 0; ro < 2; ro++) {
                const int rowl = wm * 32 + mi * 16 + g + ro * 8;
                #pragma unroll
                for (int ni = 0; ni < 4; ni++) {
                    const int cl = wn * 32 + ni * 8 + 2 * tt;
                    const float2 x = *(const float2*)(xg + (size_t)rowl * G4H + n0 + cl);
                    const float v0 = acc[mi][ni][ro * 2 + 0] + x.x + bias0[ni];
                    const float v1 = acc[mi][ni][ro * 2 + 1] + x.y + bias1[ni];
                    const float p0 = __shfl_xor_sync(0xffffffffu, v0, 1);
                    const float p1 = __shfl_xor_sync(0xffffffffu, v1, 1);
                    if ((tt & 1) == 0) {
                        const float ii = sigf(v0);
                        const float ff = sigf(v1);
                        const float gg = tanhf(p0);
                        const float oo = sigf(p1);
                        const float cn = ff * creg[mi][ni][ro] + ii * gg;
                        creg[mi][ni][ro] = cn;
                        const int kg = (n0 + cl) >> 2;
                        g_h[(size_t)(m0 + rowl) * QH + kg] = __float2bfloat16(oo * tanhf(cn));
                    }
                }
            }
        }

        if (t < T_ - 1) {
            __threadfence();
            __syncthreads();
            if (tid == 0) {
                atomicAdd(&g_bar, 1u);
                const unsigned target = 128u * (unsigned)(t + 1);
                while (atomicAdd(&g_bar, 0u) < target) { __nanosleep(64); }
            }
            __syncthreads();
        }
    }
}

// ---------------- prep kernels ----------------
__device__ __forceinline__ int lstm_src_row(int j) { return (j & 3) * QH + (j >> 2); }

__global__ void prep_x_kernel(const float* __restrict__ q_feats) {
    int idx = blockIdx.x * blockDim.x + threadIdx.x;
    if (idx >= T_ * B_ * E_PAD) return;
    int r = idx / E_PAD, e = idx % E_PAD;
    int t = r >> 8, b = r & 255;
    float v = (e < E_RAW) ? q_feats[((size_t)b * T_ + t) * E_RAW + e] : 0.f;
    g_Xbf[idx] = __float2bfloat16(v);
}

__global__ void prep_wih_kernel(const float* __restrict__ W_ih) {
    int idx = blockIdx.x * blockDim.x + threadIdx.x;
    if (idx >= G4H * E_PAD) return;
    int j = idx / E_PAD, e = idx % E_PAD;
    int src = lstm_src_row(j);
    float v = (e < E_RAW) ? W_ih[(size_t)src * E_RAW + e] : 0.f;
    g_Wih[idx] = __float2bfloat16(v);
}

__global__ void prep_whh_kernel(const float* __restrict__ W_hh) {
    int idx = blockIdx.x * blockDim.x + threadIdx.x;
    if (idx >= G4H * QH) return;
    int j = idx >> 10, e = idx & 1023;
    int src = lstm_src_row(j);
    g_Whh[idx] = __float2bfloat16(W_hh[(size_t)src * QH + e]);
}

__global__ void prep_bias_kernel(const float* __restrict__ b_ih, const float* __restrict__ b_hh) {
    int j = blockIdx.x * blockDim.x + threadIdx.x;
    if (j == 0) g_bar = 0u;
    if (j >= G4H) return;
    int src = lstm_src_row(j);
    g_bias[j] = b_ih[src] + b_hh[src];
}

// single-block scan: build compacted row list from index[]
__global__ void rowmap_kernel(const int* __restrict__ index) {
    __shared__ int sc[B_];
    const int b = threadIdx.x;   // 256 threads
    int cnt = index[b];
    cnt = max(0, min(cnt, MAXN_));
    sc[b] = cnt;
    __syncthreads();
    for (int off = 1; off < B_; off <<= 1) {
        int v = (b >= off) ? sc[b - off] : 0;
        __syncthreads();
        sc[b] += v;
        __syncthreads();
    }
    const int pref = sc[b] - cnt;
    g_prefix[b] = pref;
    for (int j = 0; j < cnt; j++) {
        g_rowsrc[pref + j] = b * MAXN_ + j;
        g_rowb[pref + j]   = b;
    }
    const int total = sc[B_ - 1];
    const int pad = (total + 127) & ~127;
    if (b == 0) { g_nrows = total; g_nrowsPad = pad; }
    for (int j = total + b; j < pad; j += B_) g_rowb[j] = 0;
}

__global__ void prep_wbox_kernel(const float* __restrict__ W_w, const float* __restrict__ Wp_w) {
    int idx = blockIdx.x * blockDim.x + threadIdx.x;
    if (idx >= NBIG * ICNN) return;
    int j = idx >> 11, cc = idx & 2047;
    int h = j >> 1;
    const float* s = (j & 1) ? Wp_w : W_w;
    g_Wbox[idx] = __float2bfloat16(s[(size_t)h * (ICNN + QH) + cc]);
}

__global__ void prep_wq_kernel(const float* __restrict__ W_w, const float* __restrict__ Wp_w) {
    int idx = blockIdx.x * blockDim.x + threadIdx.x;
    if (idx >= NBIG * QH) return;
    int j = idx >> 10, cc = idx & 1023;
    int h = j >> 1;
    const float* s = (j & 1) ? Wp_w : W_w;
    g_Wq[idx] = __float2bfloat16(s[(size_t)h * (ICNN + QH) + ICNN + cc]);
}

__global__ void prep_small_kernel(const float* __restrict__ W_b, const float* __restrict__ Wp_b,
                                  const float* __restrict__ f_w) {
    int idx = blockIdx.x * blockDim.x + threadIdx.x;
    if (idx < NBIG) {
        g_mb[idx] = (idx & 1) ? Wp_b[idx >> 1] : W_b[idx >> 1];
    } else if (idx < NBIG + HID_) {
        g_fw[idx - NBIG] = f_w[idx - NBIG];
    }
}

// gather + convert only valid box rows (zero padded tail rows)
__global__ void conv_boxc_kernel(const float* __restrict__ box) {
    const int cr = blockIdx.x;
    if (cr >= g_nrowsPad) return;
    uint4* dst = (uint4*)(g_boxc + (size_t)cr * ICNN) + threadIdx.x;
    if (cr < g_nrows) {
        const float4* src = (const float4*)(box + (size_t)g_rowsrc[cr] * ICNN) + threadIdx.x * 2;
        float4 a = src[0];
        float4 c = src[1];
        uint4 o;
        __nv_bfloat162 p;
        p = __floats2bfloat162_rn(a.x, a.y); o.x = *(uint32_t*)&p;
        p = __floats2bfloat162_rn(a.z, a.w); o.y = *(uint32_t*)&p;
        p = __floats2bfloat162_rn(c.x, c.y); o.z = *(uint32_t*)&p;
        p = __floats2bfloat162_rn(c.z, c.w); o.w = *(uint32_t*)&p;
        dst[0] = o;
    } else {
        dst[0] = make_uint4(0u, 0u, 0u, 0u);
    }
}

// ---------------- final: per-row sum of 32 partials + sigmoid + ragged sum ----------------
__global__ void final_kernel(const int* __restrict__ index, float* __restrict__ out) {
    const int b = blockIdx.x;
    const int lane = threadIdx.x;
    int cnt = index[b];
    cnt = max(0, min(cnt, MAXN_));
    const int pref = g_prefix[b];
    float s = 0.f;
    for (int r = lane; r < cnt; r += 32) {
        const float4* pp = (const float4*)&g_part[(size_t)(pref + r) * 32];
        float t = 0.f;
        #pragma unroll
        for (int j = 0; j < 8; j++) {
            float4 v = pp[j];
            t += (v.x + v.y) + (v.z + v.w);
        }
        s += sigf(t);
    }
    #pragma unroll
    for (int off = 16; off > 0; off >>= 1) s += __shfl_down_sync(0xffffffffu, s, off);
    if (lane == 0) out[b] = s;
}

// ---------------- launch ----------------
extern "C" void kernel_launch(void* const* d_in, const int* in_sizes, int n_in,
                              void* d_out, int out_size) {
    (void)in_sizes; (void)n_in; (void)out_size;
    const float* box_feats = (const float*)d_in[2];
    const float* q_feats   = (const float*)d_in[3];
    const int*   index     = (const int*)  d_in[5];
    const float* W_ih      = (const float*)d_in[6];
    const float* W_hh      = (const float*)d_in[7];
    const float* b_ih      = (const float*)d_in[8];
    const float* b_hh      = (const float*)d_in[9];
    const float* W_w       = (const float*)d_in[10];
    const float* W_b       = (const float*)d_in[11];
    const float* Wp_w      = (const float*)d_in[12];
    const float* Wp_b      = (const float*)d_in[13];
    const float* f_w       = (const float*)d_in[14];
    float* out = (float*)d_out;

    void* tmp;
    __nv_bfloat16 *Xbf_p, *Wih_p, *h_p, *Wq_p;
    float *Xg_p, *qp_p;
    cudaGetSymbolAddress(&tmp, g_Xbf); Xbf_p = (__nv_bfloat16*)tmp;
    cudaGetSymbolAddress(&tmp, g_Wih); Wih_p = (__nv_bfloat16*)tmp;
    cudaGetSymbolAddress(&tmp, g_h);   h_p   = (__nv_bfloat16*)tmp;
    cudaGetSymbolAddress(&tmp, g_Wq);  Wq_p  = (__nv_bfloat16*)tmp;
    cudaGetSymbolAddress(&tmp, g_Xg);  Xg_p  = (float*)tmp;
    cudaGetSymbolAddress(&tmp, g_qp);  qp_p  = (float*)tmp;

    const int smem3 = 3 * 2 * 128 * 40 * (int)sizeof(__nv_bfloat16);   // 61440
    cudaFuncSetAttribute(gemm_box_fused, cudaFuncAttributeMaxDynamicSharedMemorySize, smem3);
    cudaFuncSetAttribute(gemm_bf16_nt,  cudaFuncAttributeMaxDynamicSharedMemorySize, smem3);

    // idx0..2: LSTM input prep
    prep_x_kernel   <<<(T_ * B_ * E_PAD + 255) / 256, 256>>>(q_feats);
    prep_wih_kernel <<<(G4H * E_PAD + 255) / 256, 256>>>(W_ih);
    prep_whh_kernel <<<(G4H * QH) / 256, 256>>>(W_hh);
    // idx3: Xg GEMM (profiler's fixed capture slot lands on a real GEMM)
    gemm_bf16_nt<<<dim3(G4H / 128, (T_ * B_) / 128), 256, smem3>>>(Xbf_p, Wih_p, Xg_p, E_PAD, G4H);
    // idx4+: remaining prep
    prep_bias_kernel<<<G4H / 256, 256>>>(b_ih, b_hh);
    rowmap_kernel   <<<1, B_>>>(index);
    prep_small_kernel<<<((NBIG + HID_) + 255) / 256, 256>>>(W_b, Wp_b, f_w);
    prep_wbox_kernel<<<(NBIG * ICNN) / 256, 256>>>(W_w, Wp_w);
    prep_wq_kernel  <<<(NBIG * QH) / 256, 256>>>(W_w, Wp_w);
    conv_boxc_kernel<<<ROWS_BIG, 256>>>(box_feats);

    // LSTM chain
    lstm_persistent_kernel<<<dim3(G4H / 128, B_ / 64), 256>>>();
    gemm_bf16_nt<<<dim3(NBIG / 128, B_ / 128), 256, smem3>>>(h_p, Wq_p, qp_p, QH, NBIG);

    // fused box GEMM + score partials (compacted rows)
    gemm_box_fused<<<dim3(NBIG / 128, ROWS_BIG / 128), 256, smem3>>>();

    // ragged reduction
    final_kernel<<<B_, 32>>>(index, out);
}

// round 8
// speedup vs baseline: 1.8489x; 1.0547x over previous
#include <cuda_runtime.h>
#include <cuda_bf16.h>
#include <cstdint>
#include <cstddef>

// ---------------- problem constants ----------------
#define B_      256
#define T_      14
#define E_RAW   300
#define E_PAD   320
#define QH      1024
#define G4H     4096
#define ICNN    2048
#define MAXN_   100
#define HID_    512
#define ROWS_BIG (B_*MAXN_)   // 25600
#define NBIG     1024          // interleaved 2*HID
#define KC      64             // k-chunk per stage
#define ROWP    72             // padded row length (elements) for KC=64

// ---------------- device scratch ----------------
__device__ __align__(16) __nv_bfloat16 g_Xbf [(size_t)T_*B_*E_PAD];
__device__ __align__(16) __nv_bfloat16 g_Wih [(size_t)G4H*E_PAD];
__device__ __align__(16) __nv_bfloat16 g_Whh [(size_t)G4H*QH];
__device__ __align__(16) float         g_bias[G4H];
__device__ __align__(16) float         g_Xg  [(size_t)T_*B_*G4H];
__device__ __align__(16) __nv_bfloat16 g_h   [(size_t)B_*QH];
__device__ __align__(16) __nv_bfloat16 g_Wbox[(size_t)NBIG*ICNN];
__device__ __align__(16) __nv_bfloat16 g_Wq  [(size_t)NBIG*QH];
__device__ __align__(16) float         g_mb  [NBIG];
__device__ __align__(16) float         g_fw  [HID_];
__device__ __align__(16) float         g_qp  [(size_t)B_*NBIG];
__device__ __align__(16) __nv_bfloat16 g_boxc[(size_t)ROWS_BIG*ICNN];
__device__ __align__(16) float         g_part[(size_t)ROWS_BIG*32];
__device__ int      g_rowsrc[ROWS_BIG];
__device__ int      g_rowb  [ROWS_BIG];
__device__ int      g_prefix[B_];
__device__ int      g_nrows;
__device__ int      g_nrowsPad;
__device__ unsigned g_bar;

// ---------------- helpers ----------------
__device__ __forceinline__ void mma16816(float acc[4], const uint32_t a[4], const uint32_t b[2]) {
    asm volatile(
        "mma.sync.aligned.m16n8k16.row.col.f32.bf16.bf16.f32 "
        "{%0,%1,%2,%3}, {%4,%5,%6,%7}, {%8,%9}, {%0,%1,%2,%3};\n"
        : "+f"(acc[0]), "+f"(acc[1]), "+f"(acc[2]), "+f"(acc[3])
        : "r"(a[0]), "r"(a[1]), "r"(a[2]), "r"(a[3]), "r"(b[0]), "r"(b[1]));
}
__device__ __forceinline__ void cp_async16(void* smem, const void* gmem) {
    uint32_t sa = (uint32_t)__cvta_generic_to_shared(smem);
    asm volatile("cp.async.cg.shared.global [%0], [%1], 16;\n" :: "r"(sa), "l"(gmem));
}
#define CP_COMMIT() asm volatile("cp.async.commit_group;\n" ::)
#define CP_WAIT1()  asm volatile("cp.async.wait_group 1;\n" ::)

__device__ __forceinline__ void ldsm_x4(uint32_t* r, const __nv_bfloat16* p) {
    uint32_t a = (uint32_t)__cvta_generic_to_shared(p);
    asm volatile("ldmatrix.sync.aligned.m8n8.x4.shared.b16 {%0,%1,%2,%3}, [%4];"
                 : "=r"(r[0]), "=r"(r[1]), "=r"(r[2]), "=r"(r[3]) : "r"(a));
}

__device__ __forceinline__ float sigf(float x) { return 1.f / (1.f + __expf(-x)); }
__device__ __forceinline__ float ftanh(float x) {
    x = fminf(fmaxf(x, -15.f), 15.f);
    float e = __expf(2.f * x);
    return __fdividef(e - 1.f, e + 1.f);
}

// ============================================================================
// Generic GEMM: C = A[M,K]*B[N,K]^T (bf16->fp32), tile 128x128, k-chunk 64,
// 3-stage cp.async, dynamic smem, ldmatrix. M%128==0, N%128==0, K%64==0, K/64>=2.
// ============================================================================
__global__ __launch_bounds__(256, 2) void gemm_bf16_nt(
    const __nv_bfloat16* __restrict__ A,
    const __nv_bfloat16* __restrict__ B,
    float* __restrict__ C,
    int K, int N)
{
    extern __shared__ __align__(16) __nv_bfloat16 dyns[];
    typedef __nv_bfloat16 Tile[128][ROWP];
    Tile* sA = (Tile*)dyns;                       // 3 stages
    Tile* sB = (Tile*)(dyns + 3 * 128 * ROWP);    // 3 stages

    const int tid  = threadIdx.x;
    const int warp = tid >> 5;
    const int lane = tid & 31;
    const int wm   = warp >> 2;
    const int wn   = warp & 3;
    const int g    = lane >> 2;
    const int tt   = lane & 3;

    const int arow = lane & 15;
    const int acol = (lane >> 4) * 8;
    const int brow = ((lane >> 4) & 1) * 8 + (lane & 7);
    const int bcol = ((lane >> 3) & 1) * 8;

    const size_t m0 = (size_t)blockIdx.y * 128;
    const size_t n0 = (size_t)blockIdx.x * 128;

    const int lr = tid >> 3;          // 0..31 (row group)
    const int lc = (tid & 7) * 8;     // 0..56 (element chunk)

    const __nv_bfloat16* Ag = A + (m0 + lr) * (size_t)K + lc;
    const __nv_bfloat16* Bg = B + (n0 + lr) * (size_t)K + lc;
    const size_t str32 = 32 * (size_t)K;

    float acc[4][4][4];
    #pragma unroll
    for (int mi = 0; mi < 4; mi++)
        #pragma unroll
        for (int ni = 0; ni < 4; ni++)
            #pragma unroll
            for (int e = 0; e < 4; e++) acc[mi][ni][e] = 0.f;

    const int nk = K / KC;
    #pragma unroll
    for (int p = 0; p < 2; p++) {
        const int ko = p * KC;
        #pragma unroll
        for (int i = 0; i < 4; i++) {
            cp_async16(&sA[p][lr + 32 * i][lc], Ag + i * str32 + ko);
            cp_async16(&sB[p][lr + 32 * i][lc], Bg + i * str32 + ko);
        }
        CP_COMMIT();
    }

    int s2 = 2;
    for (int k = 0; k < nk; k++) {
        CP_WAIT1();
        __syncthreads();
        if (k + 2 < nk) {
            const int ko = (k + 2) * KC;
            #pragma unroll
            for (int i = 0; i < 4; i++) {
                cp_async16(&sA[s2][lr + 32 * i][lc], Ag + i * str32 + ko);
                cp_async16(&sB[s2][lr + 32 * i][lc], Bg + i * str32 + ko);
            }
        }
        CP_COMMIT();

        const int st = (s2 + 1 >= 3) ? (s2 + 1 - 3) : (s2 + 1);   // == k%3
        #pragma unroll
        for (int kk = 0; kk < 4; kk++) {
            const int kb = kk * 16;
            uint32_t af[4][4];
            #pragma unroll
            for (int mi = 0; mi < 4; mi++)
                ldsm_x4(af[mi], &sA[st][wm * 64 + mi * 16 + arow][kb + acol]);
            uint32_t bfr[4][2];
            #pragma unroll
            for (int nj = 0; nj < 2; nj++) {
                uint32_t bt[4];
                ldsm_x4(bt, &sB[st][wn * 32 + nj * 16 + brow][kb + bcol]);
                bfr[2*nj][0] = bt[0]; bfr[2*nj][1] = bt[1];
                bfr[2*nj+1][0] = bt[2]; bfr[2*nj+1][1] = bt[3];
            }
            #pragma unroll
            for (int mi = 0; mi < 4; mi++)
                #pragma unroll
                for (int ni = 0; ni < 4; ni++)
                    mma16816(acc[mi][ni], af[mi], bfr[ni]);
        }
        s2 = (s2 + 1 >= 3) ? 0 : (s2 + 1);
    }

    #pragma unroll
    for (int mi = 0; mi < 4; mi++) {
        const size_t row = m0 + wm * 64 + mi * 16 + g;
        #pragma unroll
        for (int ni = 0; ni < 4; ni++) {
            const size_t col = n0 + wn * 32 + ni * 8 + tt * 2;
            *(float2*)&C[row       * (size_t)N + col] = make_float2(acc[mi][ni][0], acc[mi][ni][1]);
            *(float2*)&C[(row + 8) * (size_t)N + col] = make_float2(acc[mi][ni][2], acc[mi][ni][3]);
        }
    }
}

// ============================================================================
// Fused box GEMM + score partial epilogue (compacted rows), k-chunk 64, 3-stage.
// ============================================================================
__global__ __launch_bounds__(256, 2) void gemm_box_fused()
{
    extern __shared__ __align__(16) __nv_bfloat16 dyns[];
    typedef __nv_bfloat16 Tile[128][ROWP];
    Tile* sA = (Tile*)dyns;
    Tile* sB = (Tile*)(dyns + 3 * 128 * ROWP);

    const int m0 = blockIdx.y * 128;
    if (m0 >= g_nrowsPad) return;

    const int tid  = threadIdx.x;
    const int warp = tid >> 5;
    const int lane = tid & 31;
    const int wm   = warp >> 2;
    const int wn   = warp & 3;
    const int g    = lane >> 2;
    const int tt   = lane & 3;
    const int n0   = blockIdx.x * 128;

    const int arow = lane & 15;
    const int acol = (lane >> 4) * 8;
    const int brow = ((lane >> 4) & 1) * 8 + (lane & 7);
    const int bcol = ((lane >> 3) & 1) * 8;

    const int lr = tid >> 3;
    const int lc = (tid & 7) * 8;

    const __nv_bfloat16* Ag = g_boxc + (size_t)(m0 + lr) * ICNN + lc;
    const __nv_bfloat16* Bg = g_Wbox + (size_t)(n0 + lr) * ICNN + lc;
    const size_t str32 = 32 * (size_t)ICNN;

    float acc[4][4][4];
    #pragma unroll
    for (int mi = 0; mi < 4; mi++)
        #pragma unroll
        for (int ni = 0; ni < 4; ni++)
            #pragma unroll
            for (int e = 0; e < 4; e++) acc[mi][ni][e] = 0.f;

    const int nk = ICNN / KC;   // 32

    #pragma unroll
    for (int p = 0; p < 2; p++) {
        const int ko = p * KC;
        #pragma unroll
        for (int i = 0; i < 4; i++) {
            cp_async16(&sA[p][lr + 32 * i][lc], Ag + i * str32 + ko);
            cp_async16(&sB[p][lr + 32 * i][lc], Bg + i * str32 + ko);
        }
        CP_COMMIT();
    }

    int s2 = 2;
    for (int k = 0; k < nk; k++) {
        CP_WAIT1();
        __syncthreads();
        if (k + 2 < nk) {
            const int ko = (k + 2) * KC;
            #pragma unroll
            for (int i = 0; i < 4; i++) {
                cp_async16(&sA[s2][lr + 32 * i][lc], Ag + i * str32 + ko);
                cp_async16(&sB[s2][lr + 32 * i][lc], Bg + i * str32 + ko);
            }
        }
        CP_COMMIT();

        const int st = (s2 + 1 >= 3) ? (s2 + 1 - 3) : (s2 + 1);
        #pragma unroll
        for (int kk = 0; kk < 4; kk++) {
            const int kb = kk * 16;
            uint32_t af[4][4];
            #pragma unroll
            for (int mi = 0; mi < 4; mi++)
                ldsm_x4(af[mi], &sA[st][wm * 64 + mi * 16 + arow][kb + acol]);
            uint32_t bfr[4][2];
            #pragma unroll
            for (int nj = 0; nj < 2; nj++) {
                uint32_t bt[4];
                ldsm_x4(bt, &sB[st][wn * 32 + nj * 16 + brow][kb + bcol]);
                bfr[2*nj][0] = bt[0]; bfr[2*nj][1] = bt[1];
                bfr[2*nj+1][0] = bt[2]; bfr[2*nj+1][1] = bt[3];
            }
            #pragma unroll
            for (int mi = 0; mi < 4; mi++)
                #pragma unroll
                for (int ni = 0; ni < 4; ni++)
                    mma16816(acc[mi][ni], af[mi], bfr[ni]);
        }
        s2 = (s2 + 1 >= 3) ? 0 : (s2 + 1);
    }

    // ---------------- fused score epilogue ----------------
    float fwv[4];
    float2 mbv[4];
    #pragma unroll
    for (int ni = 0; ni < 4; ni++) {
        const int col = n0 + wn * 32 + ni * 8 + tt * 2;
        fwv[ni] = g_fw[col >> 1];
        mbv[ni] = *(const float2*)&g_mb[col];
    }

    #pragma unroll
    for (int mi = 0; mi < 4; mi++) {
        #pragma unroll
        for (int ro = 0; ro < 2; ro++) {
            const int row = m0 + wm * 64 + mi * 16 + g + ro * 8;
            const int b = g_rowb[row];
            const float* qpb = g_qp + (size_t)b * NBIG;
            float p = 0.f;
            #pragma unroll
            for (int ni = 0; ni < 4; ni++) {
                const float2 q = *(const float2*)&qpb[n0 + wn * 32 + ni * 8 + tt * 2];
                const float z1 = acc[mi][ni][ro * 2 + 0] + q.x + mbv[ni].x;
                const float z2 = acc[mi][ni][ro * 2 + 1] + q.y + mbv[ni].y;
                p += fwv[ni] * ftanh(z1) * sigf(z2);
            }
            p += __shfl_xor_sync(0xffffffffu, p, 1);
            p += __shfl_xor_sync(0xffffffffu, p, 2);
            if (tt == 0) g_part[(size_t)row * 32 + blockIdx.x * 4 + wn] = p;
        }
    }
}

// ============================================================================
// Persistent fused LSTM: 14 steps, grid barrier, c in regs, k-chunk 64, 3-stage.
// Dynamic smem: 3*(64 + 128)*ROWP*2 bytes.
// ============================================================================
__global__ __launch_bounds__(256) void lstm_persistent_kernel()
{
    extern __shared__ __align__(16) __nv_bfloat16 dynl[];
    typedef __nv_bfloat16 TileA[64][ROWP];
    typedef __nv_bfloat16 TileB[128][ROWP];
    TileA* sA = (TileA*)dynl;                      // 3 stages
    TileB* sB = (TileB*)(dynl + 3 * 64 * ROWP);    // 3 stages

    const int tid  = threadIdx.x;
    const int warp = tid >> 5;
    const int lane = tid & 31;
    const int wm   = warp >> 2;
    const int wn   = warp & 3;
    const int g    = lane >> 2;
    const int tt   = lane & 3;

    const int arow = lane & 15;
    const int acol = (lane >> 4) * 8;
    const int brow = ((lane >> 4) & 1) * 8 + (lane & 7);
    const int bcol = ((lane >> 3) & 1) * 8;

    const int m0 = blockIdx.y * 64;
    const int n0 = blockIdx.x * 128;

    const int lr = tid >> 3;
    const int lc = (tid & 7) * 8;

    const __nv_bfloat16* Ag = g_h   + (size_t)(m0 + lr) * QH + lc;
    const __nv_bfloat16* Bg = g_Whh + (size_t)(n0 + lr) * QH + lc;
    const size_t str32 = 32 * (size_t)QH;

    float bias0[4], bias1[4];
    #pragma unroll
    for (int ni = 0; ni < 4; ni++) {
        const int c = n0 + wn * 32 + ni * 8 + 2 * tt;
        bias0[ni] = g_bias[c];
        bias1[ni] = g_bias[c + 1];
    }

    float creg[2][4][2];
    #pragma unroll
    for (int mi = 0; mi < 2; mi++)
        #pragma unroll
        for (int ni = 0; ni < 4; ni++) { creg[mi][ni][0] = 0.f; creg[mi][ni][1] = 0.f; }

    for (int t = 0; t < T_; t++) {
        float acc[2][4][4];
        #pragma unroll
        for (int mi = 0; mi < 2; mi++)
            #pragma unroll
            for (int ni = 0; ni < 4; ni++)
                #pragma unroll
                for (int e = 0; e < 4; e++) acc[mi][ni][e] = 0.f;

        if (t > 0) {
            const int nk = QH / KC;   // 16
            #pragma unroll
            for (int p = 0; p < 2; p++) {
                const int ko = p * KC;
                #pragma unroll
                for (int i = 0; i < 2; i++)
                    cp_async16(&sA[p][lr + 32 * i][lc], Ag + i * str32 + ko);
                #pragma unroll
                for (int i = 0; i < 4; i++)
                    cp_async16(&sB[p][lr + 32 * i][lc], Bg + i * str32 + ko);
                CP_COMMIT();
            }
            int s2 = 2;
            for (int k = 0; k < nk; k++) {
                CP_WAIT1();
                __syncthreads();
                if (k + 2 < nk) {
                    const int ko = (k + 2) * KC;
                    #pragma unroll
                    for (int i = 0; i < 2; i++)
                        cp_async16(&sA[s2][lr + 32 * i][lc], Ag + i * str32 + ko);
                    #pragma unroll
                    for (int i = 0; i < 4; i++)
                        cp_async16(&sB[s2][lr + 32 * i][lc], Bg + i * str32 + ko);
                }
                CP_COMMIT();

                const int st = (s2 + 1 >= 3) ? (s2 + 1 - 3) : (s2 + 1);
                #pragma unroll
                for (int kk = 0; kk < 4; kk++) {
                    const int kb = kk * 16;
                    uint32_t af[2][4];
                    #pragma unroll
                    for (int mi = 0; mi < 2; mi++)
                        ldsm_x4(af[mi], &sA[st][wm * 32 + mi * 16 + arow][kb + acol]);
                    uint32_t bfr[4][2];
                    #pragma unroll
                    for (int nj = 0; nj < 2; nj++) {
                        uint32_t bt[4];
                        ldsm_x4(bt, &sB[st][wn * 32 + nj * 16 + brow][kb + bcol]);
                        bfr[2*nj][0] = bt[0]; bfr[2*nj][1] = bt[1];
                        bfr[2*nj+1][0] = bt[2]; bfr[2*nj+1][1] = bt[3];
                    }
                    #pragma unroll
                    for (int mi = 0; mi < 2; mi++)
                        #pragma unroll
                        for (int ni = 0; ni < 4; ni++)
                            mma16816(acc[mi][ni], af[mi], bfr[ni]);
                }
                s2 = (s2 + 1 >= 3) ? 0 : (s2 + 1);
            }
        }

        const float* xg = g_Xg + (size_t)(t * B_ + m0) * G4H;
        #pragma unroll
        for (int mi = 0; mi < 2; mi++) {
            #pragma unroll
            for (int ro = 0; ro < 2; ro++) {
                const int rowl = wm * 32 + mi * 16 + g + ro * 8;
                #pragma unroll
                for (int ni = 0; ni < 4; ni++) {
                    const int cl = wn * 32 + ni * 8 + 2 * tt;
                    const float2 x = *(const float2*)(xg + (size_t)rowl * G4H + n0 + cl);
                    const float v0 = acc[mi][ni][ro * 2 + 0] + x.x + bias0[ni];
                    const float v1 = acc[mi][ni][ro * 2 + 1] + x.y + bias1[ni];
                    const float p0 = __shfl_xor_sync(0xffffffffu, v0, 1);
                    const float p1 = __shfl_xor_sync(0xffffffffu, v1, 1);
                    if ((tt & 1) == 0) {
                        const float ii = sigf(v0);
                        const float ff = sigf(v1);
                        const float gg = tanhf(p0);
                        const float oo = sigf(p1);
                        const float cn = ff * creg[mi][ni][ro] + ii * gg;
                        creg[mi][ni][ro] = cn;
                        const int kg = (n0 + cl) >> 2;
                        g_h[(size_t)(m0 + rowl) * QH + kg] = __float2bfloat16(oo * tanhf(cn));
                    }
                }
            }
        }

        if (t < T_ - 1) {
            __threadfence();
            __syncthreads();
            if (tid == 0) {
                atomicAdd(&g_bar, 1u);
                const unsigned target = 128u * (unsigned)(t + 1);
                while (atomicAdd(&g_bar, 0u) < target) { __nanosleep(64); }
            }
            __syncthreads();
        }
    }
}

// ---------------- prep kernels ----------------
__device__ __forceinline__ int lstm_src_row(int j) { return (j & 3) * QH + (j >> 2); }

__global__ void prep_x_kernel(const float* __restrict__ q_feats) {
    int idx = blockIdx.x * blockDim.x + threadIdx.x;
    if (idx >= T_ * B_ * E_PAD) return;
    int r = idx / E_PAD, e = idx % E_PAD;
    int t = r >> 8, b = r & 255;
    float v = (e < E_RAW) ? q_feats[((size_t)b * T_ + t) * E_RAW + e] : 0.f;
    g_Xbf[idx] = __float2bfloat16(v);
}

__global__ void prep_wih_kernel(const float* __restrict__ W_ih) {
    int idx = blockIdx.x * blockDim.x + threadIdx.x;
    if (idx >= G4H * E_PAD) return;
    int j = idx / E_PAD, e = idx % E_PAD;
    int src = lstm_src_row(j);
    float v = (e < E_RAW) ? W_ih[(size_t)src * E_RAW + e] : 0.f;
    g_Wih[idx] = __float2bfloat16(v);
}

__global__ void prep_whh_kernel(const float* __restrict__ W_hh) {
    int idx = blockIdx.x * blockDim.x + threadIdx.x;
    if (idx >= G4H * QH) return;
    int j = idx >> 10, e = idx & 1023;
    int src = lstm_src_row(j);
    g_Whh[idx] = __float2bfloat16(W_hh[(size_t)src * QH + e]);
}

__global__ void prep_bias_kernel(const float* __restrict__ b_ih, const float* __restrict__ b_hh) {
    int j = blockIdx.x * blockDim.x + threadIdx.x;
    if (j == 0) g_bar = 0u;
    if (j >= G4H) return;
    int src = lstm_src_row(j);
    g_bias[j] = b_ih[src] + b_hh[src];
}

// single-block scan: build compacted row list from index[]
__global__ void rowmap_kernel(const int* __restrict__ index) {
    __shared__ int sc[B_];
    const int b = threadIdx.x;
    int cnt = index[b];
    cnt = max(0, min(cnt, MAXN_));
    sc[b] = cnt;
    __syncthreads();
    for (int off = 1; off < B_; off <<= 1) {
        int v = (b >= off) ? sc[b - off] : 0;
        __syncthreads();
        sc[b] += v;
        __syncthreads();
    }
    const int pref = sc[b] - cnt;
    g_prefix[b] = pref;
    for (int j = 0; j < cnt; j++) {
        g_rowsrc[pref + j] = b * MAXN_ + j;
        g_rowb[pref + j]   = b;
    }
    const int total = sc[B_ - 1];
    const int pad = (total + 127) & ~127;
    if (b == 0) { g_nrows = total; g_nrowsPad = pad; }
    for (int j = total + b; j < pad; j += B_) g_rowb[j] = 0;
}

__global__ void prep_wbox_kernel(const float* __restrict__ W_w, const float* __restrict__ Wp_w) {
    int idx = blockIdx.x * blockDim.x + threadIdx.x;
    if (idx >= NBIG * ICNN) return;
    int j = idx >> 11, cc = idx & 2047;
    int h = j >> 1;
    const float* s = (j & 1) ? Wp_w : W_w;
    g_Wbox[idx] = __float2bfloat16(s[(size_t)h * (ICNN + QH) + cc]);
}

__global__ void prep_wq_kernel(const float* __restrict__ W_w, const float* __restrict__ Wp_w) {
    int idx = blockIdx.x * blockDim.x + threadIdx.x;
    if (idx >= NBIG * QH) return;
    int j = idx >> 10, cc = idx & 1023;
    int h = j >> 1;
    const float* s = (j & 1) ? Wp_w : W_w;
    g_Wq[idx] = __float2bfloat16(s[(size_t)h * (ICNN + QH) + ICNN + cc]);
}

__global__ void prep_small_kernel(const float* __restrict__ W_b, const float* __restrict__ Wp_b,
                                  const float* __restrict__ f_w) {
    int idx = blockIdx.x * blockDim.x + threadIdx.x;
    if (idx < NBIG) {
        g_mb[idx] = (idx & 1) ? Wp_b[idx >> 1] : W_b[idx >> 1];
    } else if (idx < NBIG + HID_) {
        g_fw[idx - NBIG] = f_w[idx - NBIG];
    }
}

// gather + convert only valid box rows (zero padded tail rows)
__global__ void conv_boxc_kernel(const float* __restrict__ box) {
    const int cr = blockIdx.x;
    if (cr >= g_nrowsPad) return;
    uint4* dst = (uint4*)(g_boxc + (size_t)cr * ICNN) + threadIdx.x;
    if (cr < g_nrows) {
        const float4* src = (const float4*)(box + (size_t)g_rowsrc[cr] * ICNN) + threadIdx.x * 2;
        float4 a = src[0];
        float4 c = src[1];
        uint4 o;
        __nv_bfloat162 p;
        p = __floats2bfloat162_rn(a.x, a.y); o.x = *(uint32_t*)&p;
        p = __floats2bfloat162_rn(a.z, a.w); o.y = *(uint32_t*)&p;
        p = __floats2bfloat162_rn(c.x, c.y); o.z = *(uint32_t*)&p;
        p = __floats2bfloat162_rn(c.z, c.w); o.w = *(uint32_t*)&p;
        dst[0] = o;
    } else {
        dst[0] = make_uint4(0u, 0u, 0u, 0u);
    }
}

// ---------------- final: per-row sum of 32 partials + sigmoid + ragged sum ----------------
__global__ void final_kernel(const int* __restrict__ index, float* __restrict__ out) {
    const int b = blockIdx.x;
    const int lane = threadIdx.x;
    int cnt = index[b];
    cnt = max(0, min(cnt, MAXN_));
    const int pref = g_prefix[b];
    float s = 0.f;
    for (int r = lane; r < cnt; r += 32) {
        const float4* pp = (const float4*)&g_part[(size_t)(pref + r) * 32];
        float t = 0.f;
        #pragma unroll
        for (int j = 0; j < 8; j++) {
            float4 v = pp[j];
            t += (v.x + v.y) + (v.z + v.w);
        }
        s += sigf(t);
    }
    #pragma unroll
    for (int off = 16; off > 0; off >>= 1) s += __shfl_down_sync(0xffffffffu, s, off);
    if (lane == 0) out[b] = s;
}

// ---------------- launch ----------------
extern "C" void kernel_launch(void* const* d_in, const int* in_sizes, int n_in,
                              void* d_out, int out_size) {
    (void)in_sizes; (void)n_in; (void)out_size;
    const float* box_feats = (const float*)d_in[2];
    const float* q_feats   = (const float*)d_in[3];
    const int*   index     = (const int*)  d_in[5];
    const float* W_ih      = (const float*)d_in[6];
    const float* W_hh      = (const float*)d_in[7];
    const float* b_ih      = (const float*)d_in[8];
    const float* b_hh      = (const float*)d_in[9];
    const float* W_w       = (const float*)d_in[10];
    const float* W_b       = (const float*)d_in[11];
    const float* Wp_w      = (const float*)d_in[12];
    const float* Wp_b      = (const float*)d_in[13];
    const float* f_w       = (const float*)d_in[14];
    float* out = (float*)d_out;

    void* tmp;
    __nv_bfloat16 *Xbf_p, *Wih_p, *h_p, *Wq_p;
    float *Xg_p, *qp_p;
    cudaGetSymbolAddress(&tmp, g_Xbf); Xbf_p = (__nv_bfloat16*)tmp;
    cudaGetSymbolAddress(&tmp, g_Wih); Wih_p = (__nv_bfloat16*)tmp;
    cudaGetSymbolAddress(&tmp, g_h);   h_p   = (__nv_bfloat16*)tmp;
    cudaGetSymbolAddress(&tmp, g_Wq);  Wq_p  = (__nv_bfloat16*)tmp;
    cudaGetSymbolAddress(&tmp, g_Xg);  Xg_p  = (float*)tmp;
    cudaGetSymbolAddress(&tmp, g_qp);  qp_p  = (float*)tmp;

    const int smemG = 3 * 2 * 128 * ROWP * (int)sizeof(__nv_bfloat16);          // 110592
    const int smemL = 3 * (64 + 128) * ROWP * (int)sizeof(__nv_bfloat16);       // 82944
    cudaFuncSetAttribute(gemm_bf16_nt,   cudaFuncAttributeMaxDynamicSharedMemorySize, smemG);
    cudaFuncSetAttribute(gemm_box_fused, cudaFuncAttributeMaxDynamicSharedMemorySize, smemG);
    cudaFuncSetAttribute(lstm_persistent_kernel, cudaFuncAttributeMaxDynamicSharedMemorySize, smemL);

    // idx0..2: LSTM input prep
    prep_x_kernel   <<<(T_ * B_ * E_PAD + 255) / 256, 256>>>(q_feats);
    prep_wih_kernel <<<(G4H * E_PAD + 255) / 256, 256>>>(W_ih);
    prep_whh_kernel <<<(G4H * QH) / 256, 256>>>(W_hh);
    // idx3: Xg GEMM (profiler's fixed capture slot lands on a real GEMM)
    gemm_bf16_nt<<<dim3(G4H / 128, (T_ * B_) / 128), 256, smemG>>>(Xbf_p, Wih_p, Xg_p, E_PAD, G4H);
    // idx4+: remaining prep
    prep_bias_kernel<<<G4H / 256, 256>>>(b_ih, b_hh);
    rowmap_kernel   <<<1, B_>>>(index);
    prep_small_kernel<<<((NBIG + HID_) + 255) / 256, 256>>>(W_b, Wp_b, f_w);
    prep_wbox_kernel<<<(NBIG * ICNN) / 256, 256>>>(W_w, Wp_w);
    prep_wq_kernel  <<<(NBIG * QH) / 256, 256>>>(W_w, Wp_w);
    conv_boxc_kernel<<<ROWS_BIG, 256>>>(box_feats);

    // LSTM chain
    lstm_persistent_kernel<<<dim3(G4H / 128, B_ / 64), 256, smemL>>>();
    gemm_bf16_nt<<<dim3(NBIG / 128, B_ / 128), 256, smemG>>>(h_p, Wq_p, qp_p, QH, NBIG);

    // fused box GEMM + score partials (compacted rows)
    gemm_box_fused<<<dim3(NBIG / 128, ROWS_BIG / 128), 256, smemG>>>();

    // ragged reduction
    final_kernel<<<B_, 32>>>(index, out);
}

// round 9
// speedup vs baseline: 1.9394x; 1.0490x over previous
#include <cuda_runtime.h>
#include <cuda_bf16.h>
#include <cstdint>
#include <cstddef>

// ---------------- problem constants ----------------
#define B_      256
#define T_      14
#define E_RAW   300
#define E_PAD   320
#define QH      1024
#define G4H     4096
#define ICNN    2048
#define MAXN_   100
#define HID_    512
#define ROWS_BIG (B_*MAXN_)   // 25600
#define NBIG     1024          // interleaved 2*HID
#define KC      64             // k-chunk per stage
#define ROWP    72             // padded row length (elements) for KC=64

// ---------------- device scratch ----------------
__device__ __align__(16) __nv_bfloat16 g_Xbf [(size_t)T_*B_*E_PAD];
__device__ __align__(16) __nv_bfloat16 g_Wih [(size_t)G4H*E_PAD];
__device__ __align__(16) __nv_bfloat16 g_Whh [(size_t)G4H*QH];
__device__ __align__(16) float         g_bias[G4H];
__device__ __align__(16) float         g_Xg  [(size_t)T_*B_*G4H];
__device__ __align__(16) float         g_G   [(size_t)B_*G4H];
__device__ __align__(16) float         g_c   [(size_t)B_*QH];
__device__ __align__(16) __nv_bfloat16 g_h   [(size_t)B_*QH];
__device__ __align__(16) __nv_bfloat16 g_Wbox[(size_t)NBIG*ICNN];
__device__ __align__(16) __nv_bfloat16 g_Wq  [(size_t)NBIG*QH];
__device__ __align__(16) float         g_mb  [NBIG];
__device__ __align__(16) float         g_fw  [HID_];
__device__ __align__(16) float         g_qp  [(size_t)B_*NBIG];
__device__ __align__(16) __nv_bfloat16 g_boxc[(size_t)ROWS_BIG*ICNN];
__device__ __align__(16) float         g_Z   [(size_t)ROWS_BIG*NBIG];
__device__ __align__(16) float         g_wsi [ROWS_BIG];
__device__ int g_rowsrc[ROWS_BIG];
__device__ int g_rowb  [ROWS_BIG];
__device__ int g_prefix[B_];
__device__ int g_nrows;
__device__ int g_nrowsPad;

// ---------------- helpers ----------------
__device__ __forceinline__ void mma16816(float acc[4], const uint32_t a[4], const uint32_t b[2]) {
    asm volatile(
        "mma.sync.aligned.m16n8k16.row.col.f32.bf16.bf16.f32 "
        "{%0,%1,%2,%3}, {%4,%5,%6,%7}, {%8,%9}, {%0,%1,%2,%3};\n"
        : "+f"(acc[0]), "+f"(acc[1]), "+f"(acc[2]), "+f"(acc[3])
        : "r"(a[0]), "r"(a[1]), "r"(a[2]), "r"(a[3]), "r"(b[0]), "r"(b[1]));
}
__device__ __forceinline__ void cp_async16(void* smem, const void* gmem) {
    uint32_t sa = (uint32_t)__cvta_generic_to_shared(smem);
    asm volatile("cp.async.cg.shared.global [%0], [%1], 16;\n" :: "r"(sa), "l"(gmem));
}
#define CP_COMMIT() asm volatile("cp.async.commit_group;\n" ::)
#define CP_WAIT1()  asm volatile("cp.async.wait_group 1;\n" ::)

__device__ __forceinline__ void ldsm_x4(uint32_t* r, const __nv_bfloat16* p) {
    uint32_t a = (uint32_t)__cvta_generic_to_shared(p);
    asm volatile("ldmatrix.sync.aligned.m8n8.x4.shared.b16 {%0,%1,%2,%3}, [%4];"
                 : "=r"(r[0]), "=r"(r[1]), "=r"(r[2]), "=r"(r[3]) : "r"(a));
}

__device__ __forceinline__ float sigf(float x) { return 1.f / (1.f + __expf(-x)); }
__device__ __forceinline__ float ftanh(float x) {
    x = fminf(fmaxf(x, -15.f), 15.f);
    float e = __expf(2.f * x);
    return __fdividef(e - 1.f, e + 1.f);
}

// ============================================================================
// Generic GEMM: C = A[M,K]*B[N,K]^T (bf16->fp32), tile 128x128, k-chunk 64,
// 3-stage cp.async, dynamic smem, ldmatrix. M%128==0, N%128==0, K%64==0, K/64>=2.
// ============================================================================
__global__ __launch_bounds__(256, 2) void gemm_bf16_nt(
    const __nv_bfloat16* __restrict__ A,
    const __nv_bfloat16* __restrict__ B,
    float* __restrict__ C,
    int K, int N)
{
    extern __shared__ __align__(16) __nv_bfloat16 dyns[];
    typedef __nv_bfloat16 Tile[128][ROWP];
    Tile* sA = (Tile*)dyns;
    Tile* sB = (Tile*)(dyns + 3 * 128 * ROWP);

    const int tid  = threadIdx.x;
    const int warp = tid >> 5;
    const int lane = tid & 31;
    const int wm   = warp >> 2;
    const int wn   = warp & 3;
    const int g    = lane >> 2;
    const int tt   = lane & 3;

    const int arow = lane & 15;
    const int acol = (lane >> 4) * 8;
    const int brow = ((lane >> 4) & 1) * 8 + (lane & 7);
    const int bcol = ((lane >> 3) & 1) * 8;

    const size_t m0 = (size_t)blockIdx.y * 128;
    const size_t n0 = (size_t)blockIdx.x * 128;

    const int lr = tid >> 3;
    const int lc = (tid & 7) * 8;

    const __nv_bfloat16* Ag = A + (m0 + lr) * (size_t)K + lc;
    const __nv_bfloat16* Bg = B + (n0 + lr) * (size_t)K + lc;
    const size_t str32 = 32 * (size_t)K;

    float acc[4][4][4];
    #pragma unroll
    for (int mi = 0; mi < 4; mi++)
        #pragma unroll
        for (int ni = 0; ni < 4; ni++)
            #pragma unroll
            for (int e = 0; e < 4; e++) acc[mi][ni][e] = 0.f;

    const int nk = K / KC;
    #pragma unroll
    for (int p = 0; p < 2; p++) {
        const int ko = p * KC;
        #pragma unroll
        for (int i = 0; i < 4; i++) {
            cp_async16(&sA[p][lr + 32 * i][lc], Ag + i * str32 + ko);
            cp_async16(&sB[p][lr + 32 * i][lc], Bg + i * str32 + ko);
        }
        CP_COMMIT();
    }

    int s2 = 2;
    for (int k = 0; k < nk; k++) {
        CP_WAIT1();
        __syncthreads();
        if (k + 2 < nk) {
            const int ko = (k + 2) * KC;
            #pragma unroll
            for (int i = 0; i < 4; i++) {
                cp_async16(&sA[s2][lr + 32 * i][lc], Ag + i * str32 + ko);
                cp_async16(&sB[s2][lr + 32 * i][lc], Bg + i * str32 + ko);
            }
        }
        CP_COMMIT();

        const int st = (s2 + 1 >= 3) ? (s2 + 1 - 3) : (s2 + 1);   // == k%3
        #pragma unroll
        for (int kk = 0; kk < 4; kk++) {
            const int kb = kk * 16;
            uint32_t af[4][4];
            #pragma unroll
            for (int mi = 0; mi < 4; mi++)
                ldsm_x4(af[mi], &sA[st][wm * 64 + mi * 16 + arow][kb + acol]);
            uint32_t bfr[4][2];
            #pragma unroll
            for (int nj = 0; nj < 2; nj++) {
                uint32_t bt[4];
                ldsm_x4(bt, &sB[st][wn * 32 + nj * 16 + brow][kb + bcol]);
                bfr[2*nj][0] = bt[0]; bfr[2*nj][1] = bt[1];
                bfr[2*nj+1][0] = bt[2]; bfr[2*nj+1][1] = bt[3];
            }
            #pragma unroll
            for (int mi = 0; mi < 4; mi++)
                #pragma unroll
                for (int ni = 0; ni < 4; ni++)
                    mma16816(acc[mi][ni], af[mi], bfr[ni]);
        }
        s2 = (s2 + 1 >= 3) ? 0 : (s2 + 1);
    }

    #pragma unroll
    for (int mi = 0; mi < 4; mi++) {
        const size_t row = m0 + wm * 64 + mi * 16 + g;
        #pragma unroll
        for (int ni = 0; ni < 4; ni++) {
            const size_t col = n0 + wn * 32 + ni * 8 + tt * 2;
            *(float2*)&C[row       * (size_t)N + col] = make_float2(acc[mi][ni][0], acc[mi][ni][1]);
            *(float2*)&C[(row + 8) * (size_t)N + col] = make_float2(acc[mi][ni][2], acc[mi][ni][3]);
        }
    }
}

// ============================================================================
// Box GEMM: Z = boxc * Wbox^T (compacted rows, early-exit past nrowsPad).
// Identical mainloop to gemm_bf16_nt, fixed operands.
// ============================================================================
__global__ __launch_bounds__(256, 2) void gemm_boxZ_kernel()
{
    extern __shared__ __align__(16) __nv_bfloat16 dyns[];
    typedef __nv_bfloat16 Tile[128][ROWP];
    Tile* sA = (Tile*)dyns;
    Tile* sB = (Tile*)(dyns + 3 * 128 * ROWP);

    const int m0 = blockIdx.y * 128;
    if (m0 >= g_nrowsPad) return;

    const int tid  = threadIdx.x;
    const int warp = tid >> 5;
    const int lane = tid & 31;
    const int wm   = warp >> 2;
    const int wn   = warp & 3;
    const int g    = lane >> 2;
    const int tt   = lane & 3;
    const int n0   = blockIdx.x * 128;

    const int arow = lane & 15;
    const int acol = (lane >> 4) * 8;
    const int brow = ((lane >> 4) & 1) * 8 + (lane & 7);
    const int bcol = ((lane >> 3) & 1) * 8;

    const int lr = tid >> 3;
    const int lc = (tid & 7) * 8;

    const __nv_bfloat16* Ag = g_boxc + (size_t)(m0 + lr) * ICNN + lc;
    const __nv_bfloat16* Bg = g_Wbox + (size_t)(n0 + lr) * ICNN + lc;
    const size_t str32 = 32 * (size_t)ICNN;

    float acc[4][4][4];
    #pragma unroll
    for (int mi = 0; mi < 4; mi++)
        #pragma unroll
        for (int ni = 0; ni < 4; ni++)
            #pragma unroll
            for (int e = 0; e < 4; e++) acc[mi][ni][e] = 0.f;

    const int nk = ICNN / KC;   // 32
    #pragma unroll
    for (int p = 0; p < 2; p++) {
        const int ko = p * KC;
        #pragma unroll
        for (int i = 0; i < 4; i++) {
            cp_async16(&sA[p][lr + 32 * i][lc], Ag + i * str32 + ko);
            cp_async16(&sB[p][lr + 32 * i][lc], Bg + i * str32 + ko);
        }
        CP_COMMIT();
    }

    int s2 = 2;
    for (int k = 0; k < nk; k++) {
        CP_WAIT1();
        __syncthreads();
        if (k + 2 < nk) {
            const int ko = (k + 2) * KC;
            #pragma unroll
            for (int i = 0; i < 4; i++) {
                cp_async16(&sA[s2][lr + 32 * i][lc], Ag + i * str32 + ko);
                cp_async16(&sB[s2][lr + 32 * i][lc], Bg + i * str32 + ko);
            }
        }
        CP_COMMIT();

        const int st = (s2 + 1 >= 3) ? (s2 + 1 - 3) : (s2 + 1);
        #pragma unroll
        for (int kk = 0; kk < 4; kk++) {
            const int kb = kk * 16;
            uint32_t af[4][4];
            #pragma unroll
            for (int mi = 0; mi < 4; mi++)
                ldsm_x4(af[mi], &sA[st][wm * 64 + mi * 16 + arow][kb + acol]);
            uint32_t bfr[4][2];
            #pragma unroll
            for (int nj = 0; nj < 2; nj++) {
                uint32_t bt[4];
                ldsm_x4(bt, &sB[st][wn * 32 + nj * 16 + brow][kb + bcol]);
                bfr[2*nj][0] = bt[0]; bfr[2*nj][1] = bt[1];
                bfr[2*nj+1][0] = bt[2]; bfr[2*nj+1][1] = bt[3];
            }
            #pragma unroll
            for (int mi = 0; mi < 4; mi++)
                #pragma unroll
                for (int ni = 0; ni < 4; ni++)
                    mma16816(acc[mi][ni], af[mi], bfr[ni]);
        }
        s2 = (s2 + 1 >= 3) ? 0 : (s2 + 1);
    }

    #pragma unroll
    for (int mi = 0; mi < 4; mi++) {
        const size_t row = m0 + wm * 64 + mi * 16 + g;
        #pragma unroll
        for (int ni = 0; ni < 4; ni++) {
            const size_t col = n0 + wn * 32 + ni * 8 + tt * 2;
            *(float2*)&g_Z[row       * (size_t)NBIG + col] = make_float2(acc[mi][ni][0], acc[mi][ni][1]);
            *(float2*)&g_Z[(row + 8) * (size_t)NBIG + col] = make_float2(acc[mi][ni][2], acc[mi][ni][3]);
        }
    }
}

// ---------------- LSTM cell (after recurrent GEMM; t=0 skips G/c) ----------------
__global__ void lstm_cell_kernel(int t) {
    int idx = blockIdx.x * blockDim.x + threadIdx.x;   // exactly B_*QH threads
    int b = idx >> 10;
    int k = idx & 1023;
    size_t base = (size_t)b * G4H + 4 * (size_t)k;
    float4 xv = *(const float4*)(g_Xg + (size_t)t * B_ * G4H + base);
    float4 bv = *(const float4*)(g_bias + 4 * k);
    float vi = xv.x + bv.x;
    float vf = xv.y + bv.y;
    float vg = xv.z + bv.z;
    float vo = xv.w + bv.w;
    float cprev = 0.f;
    if (t > 0) {
        float4 gv = *(const float4*)(g_G + base);
        vi += gv.x; vf += gv.y; vg += gv.z; vo += gv.w;
        cprev = g_c[idx];
    }
    float ii = sigf(vi);
    float ff = sigf(vf);
    float gg = tanhf(vg);
    float oo = sigf(vo);
    float cn = ff * cprev + ii * gg;
    g_c[idx] = cn;
    g_h[(size_t)b * QH + k] = __float2bfloat16(oo * tanhf(cn));
}

// ---------------- prep kernels ----------------
__device__ __forceinline__ int lstm_src_row(int j) { return (j & 3) * QH + (j >> 2); }

__global__ void prep_x_kernel(const float* __restrict__ q_feats) {
    int idx = blockIdx.x * blockDim.x + threadIdx.x;
    if (idx >= T_ * B_ * E_PAD) return;
    int r = idx / E_PAD, e = idx % E_PAD;
    int t = r >> 8, b = r & 255;
    float v = (e < E_RAW) ? q_feats[((size_t)b * T_ + t) * E_RAW + e] : 0.f;
    g_Xbf[idx] = __float2bfloat16(v);
}

__global__ void prep_wih_kernel(const float* __restrict__ W_ih) {
    int idx = blockIdx.x * blockDim.x + threadIdx.x;
    if (idx >= G4H * E_PAD) return;
    int j = idx / E_PAD, e = idx % E_PAD;
    int src = lstm_src_row(j);
    float v = (e < E_RAW) ? W_ih[(size_t)src * E_RAW + e] : 0.f;
    g_Wih[idx] = __float2bfloat16(v);
}

__global__ void prep_whh_kernel(const float* __restrict__ W_hh) {
    int idx = blockIdx.x * blockDim.x + threadIdx.x;
    if (idx >= G4H * QH) return;
    int j = idx >> 10, e = idx & 1023;
    int src = lstm_src_row(j);
    g_Whh[idx] = __float2bfloat16(W_hh[(size_t)src * QH + e]);
}

__global__ void prep_bias_kernel(const float* __restrict__ b_ih, const float* __restrict__ b_hh) {
    int j = blockIdx.x * blockDim.x + threadIdx.x;
    if (j >= G4H) return;
    int src = lstm_src_row(j);
    g_bias[j] = b_ih[src] + b_hh[src];
}

// single-block scan: build compacted row list from index[]
__global__ void rowmap_kernel(const int* __restrict__ index) {
    __shared__ int sc[B_];
    const int b = threadIdx.x;
    int cnt = index[b];
    cnt = max(0, min(cnt, MAXN_));
    sc[b] = cnt;
    __syncthreads();
    for (int off = 1; off < B_; off <<= 1) {
        int v = (b >= off) ? sc[b - off] : 0;
        __syncthreads();
        sc[b] += v;
        __syncthreads();
    }
    const int pref = sc[b] - cnt;
    g_prefix[b] = pref;
    for (int j = 0; j < cnt; j++) {
        g_rowsrc[pref + j] = b * MAXN_ + j;
        g_rowb[pref + j]   = b;
    }
    const int total = sc[B_ - 1];
    const int pad = (total + 127) & ~127;
    if (b == 0) { g_nrows = total; g_nrowsPad = pad; }
    for (int j = total + b; j < pad; j += B_) g_rowb[j] = 0;
}

__global__ void prep_wbox_kernel(const float* __restrict__ W_w, const float* __restrict__ Wp_w) {
    int idx = blockIdx.x * blockDim.x + threadIdx.x;
    if (idx >= NBIG * ICNN) return;
    int j = idx >> 11, cc = idx & 2047;
    int h = j >> 1;
    const float* s = (j & 1) ? Wp_w : W_w;
    g_Wbox[idx] = __float2bfloat16(s[(size_t)h * (ICNN + QH) + cc]);
}

__global__ void prep_wq_kernel(const float* __restrict__ W_w, const float* __restrict__ Wp_w) {
    int idx = blockIdx.x * blockDim.x + threadIdx.x;
    if (idx >= NBIG * QH) return;
    int j = idx >> 10, cc = idx & 1023;
    int h = j >> 1;
    const float* s = (j & 1) ? Wp_w : W_w;
    g_Wq[idx] = __float2bfloat16(s[(size_t)h * (ICNN + QH) + ICNN + cc]);
}

__global__ void prep_small_kernel(const float* __restrict__ W_b, const float* __restrict__ Wp_b,
                                  const float* __restrict__ f_w) {
    int idx = blockIdx.x * blockDim.x + threadIdx.x;
    if (idx < NBIG) {
        g_mb[idx] = (idx & 1) ? Wp_b[idx >> 1] : W_b[idx >> 1];
    } else if (idx < NBIG + HID_) {
        g_fw[idx - NBIG] = f_w[idx - NBIG];
    }
}

// gather + convert only valid box rows (zero padded tail rows)
__global__ void conv_boxc_kernel(const float* __restrict__ box) {
    const int cr = blockIdx.x;
    if (cr >= g_nrowsPad) return;
    uint4* dst = (uint4*)(g_boxc + (size_t)cr * ICNN) + threadIdx.x;
    if (cr < g_nrows) {
        const float4* src = (const float4*)(box + (size_t)g_rowsrc[cr] * ICNN) + threadIdx.x * 2;
        float4 a = src[0];
        float4 c = src[1];
        uint4 o;
        __nv_bfloat162 p;
        p = __floats2bfloat162_rn(a.x, a.y); o.x = *(uint32_t*)&p;
        p = __floats2bfloat162_rn(a.z, a.w); o.y = *(uint32_t*)&p;
        p = __floats2bfloat162_rn(c.x, c.y); o.z = *(uint32_t*)&p;
        p = __floats2bfloat162_rn(c.z, c.w); o.w = *(uint32_t*)&p;
        dst[0] = o;
    } else {
        dst[0] = make_uint4(0u, 0u, 0u, 0u);
    }
}

// ---------------- per-row score over compact rows ----------------
__global__ void score_kernel() {
    const int r = blockIdx.x;
    if (r >= g_nrows) return;
    const int b = g_rowb[r];
    const float* zr = g_Z  + (size_t)r * NBIG;
    const float* qr = g_qp + (size_t)b * NBIG;
    float p = 0.f;
    #pragma unroll
    for (int h = threadIdx.x; h < HID_; h += 128) {
        float2 z = *(const float2*)(zr + 2 * h);
        float2 q = *(const float2*)(qr + 2 * h);
        float2 m = *(const float2*)(g_mb + 2 * h);
        float z1 = z.x + q.x + m.x;
        float z2 = z.y + q.y + m.y;
        p += g_fw[h] * ftanh(z1) * sigf(z2);
    }
    #pragma unroll
    for (int off = 16; off > 0; off >>= 1) p += __shfl_down_sync(0xffffffffu, p, off);
    __shared__ float red[4];
    if ((threadIdx.x & 31) == 0) red[threadIdx.x >> 5] = p;
    __syncthreads();
    if (threadIdx.x == 0) {
        float s = red[0] + red[1] + red[2] + red[3];
        g_wsi[r] = sigf(s);
    }
}

// ---------------- masked final sum over compact rows ----------------
__global__ void final_kernel(const int* __restrict__ index, float* __restrict__ out) {
    const int b = blockIdx.x;
    const int lane = threadIdx.x;
    int cnt = index[b];
    cnt = max(0, min(cnt, MAXN_));
    const int pref = g_prefix[b];
    float s = 0.f;
    for (int n = lane; n < cnt; n += 32) s += g_wsi[pref + n];
    #pragma unroll
    for (int off = 16; off > 0; off >>= 1) s += __shfl_down_sync(0xffffffffu, s, off);
    if (lane == 0) out[b] = s;
}

// ---------------- launch ----------------
extern "C" void kernel_launch(void* const* d_in, const int* in_sizes, int n_in,
                              void* d_out, int out_size) {
    (void)in_sizes; (void)n_in; (void)out_size;
    const float* box_feats = (const float*)d_in[2];
    const float* q_feats   = (const float*)d_in[3];
    const int*   index     = (const int*)  d_in[5];
    const float* W_ih      = (const float*)d_in[6];
    const float* W_hh      = (const float*)d_in[7];
    const float* b_ih      = (const float*)d_in[8];
    const float* b_hh      = (const float*)d_in[9];
    const float* W_w       = (const float*)d_in[10];
    const float* W_b       = (const float*)d_in[11];
    const float* Wp_w      = (const float*)d_in[12];
    const float* Wp_b      = (const float*)d_in[13];
    const float* f_w       = (const float*)d_in[14];
    float* out = (float*)d_out;

    void* tmp;
    __nv_bfloat16 *Xbf_p, *Wih_p, *Whh_p, *h_p, *Wq_p;
    float *Xg_p, *G_p, *qp_p;
    cudaGetSymbolAddress(&tmp, g_Xbf); Xbf_p = (__nv_bfloat16*)tmp;
    cudaGetSymbolAddress(&tmp, g_Wih); Wih_p = (__nv_bfloat16*)tmp;
    cudaGetSymbolAddress(&tmp, g_Whh); Whh_p = (__nv_bfloat16*)tmp;
    cudaGetSymbolAddress(&tmp, g_h);   h_p   = (__nv_bfloat16*)tmp;
    cudaGetSymbolAddress(&tmp, g_Wq);  Wq_p  = (__nv_bfloat16*)tmp;
    cudaGetSymbolAddress(&tmp, g_Xg);  Xg_p  = (float*)tmp;
    cudaGetSymbolAddress(&tmp, g_G);   G_p   = (float*)tmp;
    cudaGetSymbolAddress(&tmp, g_qp);  qp_p  = (float*)tmp;

    const int smemG = 3 * 2 * 128 * ROWP * (int)sizeof(__nv_bfloat16);   // 110592
    cudaFuncSetAttribute(gemm_bf16_nt,    cudaFuncAttributeMaxDynamicSharedMemorySize, smemG);
    cudaFuncSetAttribute(gemm_boxZ_kernel, cudaFuncAttributeMaxDynamicSharedMemorySize, smemG);

    // fork/join stream setup (host objects; created per call, leaked — few calls total)
    cudaStream_t sB;
    cudaStreamCreateWithFlags(&sB, cudaStreamNonBlocking);
    cudaEvent_t eF, eJ;
    cudaEventCreateWithFlags(&eF, cudaEventDisableTiming);
    cudaEventCreateWithFlags(&eJ, cudaEventDisableTiming);

    // ---- fork ----
    cudaEventRecord(eF, 0);
    cudaStreamWaitEvent(sB, eF, 0);

    // ---- stream B: box chain (independent of LSTM) ----
    rowmap_kernel   <<<1, B_, 0, sB>>>(index);
    prep_wbox_kernel<<<(NBIG * ICNN) / 256, 256, 0, sB>>>(W_w, Wp_w);
    conv_boxc_kernel<<<ROWS_BIG, 256, 0, sB>>>(box_feats);
    gemm_boxZ_kernel<<<dim3(NBIG / 128, ROWS_BIG / 128), 256, smemG, sB>>>();
    cudaEventRecord(eJ, sB);

    // ---- stream 0: question/LSTM chain ----
    prep_x_kernel   <<<(T_ * B_ * E_PAD + 255) / 256, 256>>>(q_feats);
    prep_wih_kernel <<<(G4H * E_PAD + 255) / 256, 256>>>(W_ih);
    prep_whh_kernel <<<(G4H * QH) / 256, 256>>>(W_hh);
    prep_bias_kernel<<<G4H / 256, 256>>>(b_ih, b_hh);
    prep_small_kernel<<<((NBIG + HID_) + 255) / 256, 256>>>(W_b, Wp_b, f_w);
    prep_wq_kernel  <<<(NBIG * QH) / 256, 256>>>(W_w, Wp_w);

    // LSTM input projections: Xg[3584,4096] = Xbf * Wih^T
    gemm_bf16_nt<<<dim3(G4H / 128, (T_ * B_) / 128), 256, smemG>>>(Xbf_p, Wih_p, Xg_p, E_PAD, G4H);

    // LSTM recurrence: 14 steps (step GEMM grids co-run with box GEMM on stream B)
    for (int t = 0; t < T_; t++) {
        if (t > 0)
            gemm_bf16_nt<<<dim3(G4H / 128, B_ / 128), 256, smemG>>>(h_p, Whh_p, G_p, QH, G4H);
        lstm_cell_kernel<<<(B_ * QH) / 256, 256>>>(t);
    }

    // question projections: qp[256,1024] = h * Wq^T
    gemm_bf16_nt<<<dim3(NBIG / 128, B_ / 128), 256, smemG>>>(h_p, Wq_p, qp_p, QH, NBIG);

    // ---- join: box Z must be complete before scoring ----
    cudaStreamWaitEvent(0, eJ, 0);

    // scores + ragged reduction
    score_kernel<<<ROWS_BIG, 128>>>();
    final_kernel<<<B_, 32>>>(index, out);
}